// round 9
// baseline (speedup 1.0000x reference)
#include <cuda_runtime.h>
#include <cstdint>

// ---------------------------------------------------------------- constants
#define BATCH 4096
#define NROWS 8192
#define DIM   256

#define QS    256.0f
#define LN2f  0.69314718055994531f
#define C2    2.8853900817779268f            // 2*log2(e)  (1/T * log2 e, T=0.5)
#define K1f   (C2 / (QS * QS))               // s32 dot -> log2-domain logit

#define BM 128                                // rows per stripe
#define BN 32                                 // cols per tile job
#define NSTRIPE (NROWS / BM)                  // 64
#define NCT     (NROWS / BN)                  // 256 col tiles per stripe
#define TT      (NSTRIPE * NCT)               // 16384 tile jobs
#define GRID    296                           // 2 CTAs per SM, exactly
#define PSLOTS  16                            // (CTAs per stripe) x 2 col-halves

#define PITCH   272                           // smem row pitch (256B data + 16B pad)
#define A_BYTES (BM * PITCH)                  // 34816
#define B_BYTES (BN * PITCH)                  // 8704
#define SMEM_A  0
#define SMEM_B0 A_BYTES
#define SMEM_B1 (A_BYTES + B_BYTES)
#define SMEM_TOTAL (A_BYTES + 2 * B_BYTES)    // 52224 -> 2 CTAs/SM

// ------------------------------------------------------------ device scratch
__device__ __align__(16) uint32_t g_q[NROWS * 64];   // int8 rows (64 u32 = 256B)
__device__ float g_ps[NROWS][PSLOTS];                // per-row partial exp2 sums
__device__ float g_diag[NROWS];                      // exact int8 self-logit
__device__ float g_pos[NROWS];                       // fp32 positive logit
__device__ float g_blk[32];

// ------------------------------------------------------------- asm helpers
__device__ __forceinline__ uint32_t smem_u32(const void* p) {
    uint32_t a;
    asm("{ .reg .u64 t; cvta.to.shared.u64 t, %1; cvt.u32.u64 %0, t; }" : "=r"(a) : "l"(p));
    return a;
}
__device__ __forceinline__ float ex2f(float x) {
    float y; asm("ex2.approx.ftz.f32 %0, %1;" : "=f"(y) : "f"(x)); return y;
}
__device__ __forceinline__ float lg2f(float x) {
    float y; asm("lg2.approx.f32 %0, %1;" : "=f"(y) : "f"(x)); return y;
}
__device__ __forceinline__ int dp4a_s32(uint32_t a, uint32_t b, int c) {
    int d;
    asm("dp4a.s32.s32 %0, %1, %2, %3;" : "=r"(d) : "r"(a), "r"(b), "r"(c));
    return d;
}
__device__ __forceinline__ void cp16(uint32_t s, const void* g) {
    asm volatile("cp.async.cg.shared.global [%0], [%1], 16;" :: "r"(s), "l"(g));
}
__device__ __forceinline__ void cp_commit() { asm volatile("cp.async.commit_group;"); }
__device__ __forceinline__ void cp_wait0()  { asm volatile("cp.async.wait_group 0;" ::: "memory"); }
__device__ __forceinline__ void ldmx4(uint32_t* r, uint32_t addr) {
    asm volatile("ldmatrix.sync.aligned.m8n8.x4.shared.b16 {%0,%1,%2,%3}, [%4];"
                 : "=r"(r[0]), "=r"(r[1]), "=r"(r[2]), "=r"(r[3]) : "r"(addr));
}
__device__ __forceinline__ void imma(int32_t* c, const uint32_t* a,
                                     uint32_t b0, uint32_t b1) {
    asm volatile("mma.sync.aligned.m16n8k32.row.col.s32.s8.s8.s32 "
                 "{%0,%1,%2,%3}, {%4,%5,%6,%7}, {%8,%9}, {%0,%1,%2,%3};"
                 : "+r"(c[0]), "+r"(c[1]), "+r"(c[2]), "+r"(c[3])
                 : "r"(a[0]), "r"(a[1]), "r"(a[2]), "r"(a[3]), "r"(b0), "r"(b1));
}
__device__ __forceinline__ uint32_t pack4(float x, float y, float z, float w) {
    int a = __float2int_rn(x), b = __float2int_rn(y);
    int c = __float2int_rn(z), d = __float2int_rn(w);
    a = max(-127, min(127, a)); b = max(-127, min(127, b));
    c = max(-127, min(127, c)); d = max(-127, min(127, d));
    return (uint32_t)(a & 255) | ((uint32_t)(b & 255) << 8) |
           ((uint32_t)(c & 255) << 16) | ((uint32_t)(d & 255) << 24);
}

// ---------------------------------------------------------------------------
// Kernel 1 (prep): one warp per pair (r, r+B).
//  - fp32 norms + cross dot  -> exact positive logit (log2 domain)
//  - int8 quantization of both normalized rows (Q=256)
//  - exact int8 self-dot (dp4a) -> diagonal logit matching the MMA
//  - zero the partial-sum slots
// ---------------------------------------------------------------------------
__global__ __launch_bounds__(256) void k_prep(const float* __restrict__ ei,
                                              const float* __restrict__ ej)
{
    int w = threadIdx.x >> 5, lane = threadIdx.x & 31;
    int r = blockIdx.x * 8 + w;                 // 0..4095

    // zero g_ps: 8192*16 = 131072 floats = exactly grid threads
    ((float*)g_ps)[blockIdx.x * 256 + threadIdx.x] = 0.f;

    const float4* A4 = (const float4*)(ei + (size_t)r * DIM);
    const float4* B4 = (const float4*)(ej + (size_t)r * DIM);
    float4 a0 = A4[lane], a1 = A4[lane + 32];
    float4 b0 = B4[lane], b1 = B4[lane + 32];

    float na = a0.x*a0.x + a0.y*a0.y + a0.z*a0.z + a0.w*a0.w
             + a1.x*a1.x + a1.y*a1.y + a1.z*a1.z + a1.w*a1.w;
    float nb = b0.x*b0.x + b0.y*b0.y + b0.z*b0.z + b0.w*b0.w
             + b1.x*b1.x + b1.y*b1.y + b1.z*b1.z + b1.w*b1.w;
    float ab = a0.x*b0.x + a0.y*b0.y + a0.z*b0.z + a0.w*b0.w
             + a1.x*b1.x + a1.y*b1.y + a1.z*b1.z + a1.w*b1.w;
    #pragma unroll
    for (int o = 16; o > 0; o >>= 1) {
        na += __shfl_xor_sync(0xFFFFFFFFu, na, o);
        nb += __shfl_xor_sync(0xFFFFFFFFu, nb, o);
        ab += __shfl_xor_sync(0xFFFFFFFFu, ab, o);
    }
    float inva = rsqrtf(na) * QS;
    float invb = rsqrtf(nb) * QS;

    uint32_t qa0 = pack4(a0.x*inva, a0.y*inva, a0.z*inva, a0.w*inva);
    uint32_t qa1 = pack4(a1.x*inva, a1.y*inva, a1.z*inva, a1.w*inva);
    uint32_t qb0 = pack4(b0.x*invb, b0.y*invb, b0.z*invb, b0.w*invb);
    uint32_t qb1 = pack4(b1.x*invb, b1.y*invb, b1.z*invb, b1.w*invb);

    g_q[(size_t)r * 64 + lane]                    = qa0;
    g_q[(size_t)r * 64 + lane + 32]               = qa1;
    g_q[(size_t)(r + BATCH) * 64 + lane]          = qb0;
    g_q[(size_t)(r + BATCH) * 64 + lane + 32]     = qb1;

    int da = dp4a_s32(qa0, qa0, dp4a_s32(qa1, qa1, 0));
    int db = dp4a_s32(qb0, qb0, dp4a_s32(qb1, qb1, 0));
    float fda = (float)da, fdb = (float)db;
    #pragma unroll
    for (int o = 16; o > 0; o >>= 1) {
        fda += __shfl_xor_sync(0xFFFFFFFFu, fda, o);
        fdb += __shfl_xor_sync(0xFFFFFFFFu, fdb, o);
    }
    if (lane == 0) {
        float pos = C2 * ab * rsqrtf(na * nb);
        g_pos[r] = pos;
        g_pos[r + BATCH] = pos;
        g_diag[r]         = fda * K1f;
        g_diag[r + BATCH] = fdb * K1f;
    }
}

// ---------------------------------------------------------------------------
// Kernel 2: persistent int8 IMMA z z^T + exp2-sum.
// 296 CTAs, each a contiguous range of the 16384 (stripe, 32-col) tile jobs.
// 8 warps = 4 row x 2 col; warp tile 32m x 16n; K=256 in 8 k32 steps.
// ---------------------------------------------------------------------------
__global__ __launch_bounds__(256, 2) void k_main()
{
    extern __shared__ char sm[];
    const uint32_t sb = smem_u32(sm);
    const int t = threadIdx.x, lane = t & 31, wid = t >> 5;
    const int wr = wid >> 1, wc = wid & 1;
    const int c = blockIdx.x;

    const int t0 = (int)(((long long)c * TT) / GRID);
    const int t1 = (int)(((long long)(c + 1) * TT) / GRID);

    // ldmatrix source addresses (b16 view of int8 tiles)
    const uint32_t a_addr0 = sb + SMEM_A
        + (uint32_t)((wr * 32 + (lane & 15)) * PITCH) + (uint32_t)((lane >> 4) * 16);
    const uint32_t a_addr1 = a_addr0 + 16 * PITCH;
    const uint32_t b_off = (uint32_t)((wc * 16 + ((lane >> 4) << 3) + (lane & 7)) * PITCH)
                         + (uint32_t)(((lane >> 3) & 1) * 16);

    int tile = t0;
    while (tile < t1) {
        const int stripe = tile >> 8;
        const int tend = min(t1, (stripe + 1) << 8);
        const int rb = stripe * BM;
        // CTA that CONTAINS the stripe's first tile anchors slot numbering;
        // each warp column-half gets its own slot (the R8 bug: halves collided).
        const int cown = (int)((((long long)(stripe << 8) + 1) * GRID - 1) / TT);
        const int slot = (c - cown) * 2 + wc;    // 0..11 (< PSLOTS)

        // load A stripe + first B tile (column tile = job index mod NCT)
        {
            const char* ga = (const char*)g_q + (size_t)rb * 256;
            #pragma unroll
            for (int it = 0; it < 8; ++it) {
                int idx = t + it * 256;
                int row = idx >> 4, ck = idx & 15;
                cp16(sb + SMEM_A + row * PITCH + ck * 16, ga + row * 256 + ck * 16);
            }
            const char* gb = (const char*)g_q
                           + (size_t)(tile & (NCT - 1)) * BN * 256;
            #pragma unroll
            for (int it = 0; it < 2; ++it) {
                int idx = t + it * 256;
                int row = idx >> 4, ck = idx & 15;
                cp16(sb + SMEM_B0 + row * PITCH + ck * 16, gb + row * 256 + ck * 16);
            }
            cp_commit(); cp_wait0(); __syncthreads();
        }

        float s[4] = {0.f, 0.f, 0.f, 0.f};

        #pragma unroll 1
        for (int tt = tile; tt < tend; ++tt) {
            const int ib = (tt - tile) & 1;
            const uint32_t bbase = sb + (ib ? SMEM_B1 : SMEM_B0);

            if (tt + 1 < tend) {
                const char* gb = (const char*)g_q
                               + (size_t)((tt + 1) & (NCT - 1)) * BN * 256;
                const uint32_t bdst = sb + (ib ? SMEM_B0 : SMEM_B1);
                #pragma unroll
                for (int it = 0; it < 2; ++it) {
                    int idx = t + it * 256;
                    int row = idx >> 4, ck = idx & 15;
                    cp16(bdst + row * PITCH + ck * 16, gb + row * 256 + ck * 16);
                }
                cp_commit();
            }

            int32_t acc[2][2][4];
            #pragma unroll
            for (int mb = 0; mb < 2; ++mb)
                #pragma unroll
                for (int nb = 0; nb < 2; ++nb)
                    #pragma unroll
                    for (int e = 0; e < 4; ++e) acc[mb][nb][e] = 0;

            #pragma unroll
            for (int ks = 0; ks < 8; ++ks) {
                uint32_t af0[4], af1[4], bf[4];
                ldmx4(af0, a_addr0 + ks * 32);
                ldmx4(af1, a_addr1 + ks * 32);
                ldmx4(bf, bbase + b_off + ks * 32);
                imma(acc[0][0], af0, bf[0], bf[1]);
                imma(acc[0][1], af0, bf[2], bf[3]);
                imma(acc[1][0], af1, bf[0], bf[1]);
                imma(acc[1][1], af1, bf[2], bf[3]);
            }

            #pragma unroll
            for (int mb = 0; mb < 2; ++mb)
                #pragma unroll
                for (int nb = 0; nb < 2; ++nb)
                    #pragma unroll
                    for (int e = 0; e < 4; ++e)
                        s[mb * 2 + (e >> 1)] += ex2f((float)acc[mb][nb][e] * K1f);

            if (tt + 1 < tend) { cp_wait0(); __syncthreads(); }
        }

        // flush row partials: 4 lanes share each row
        #pragma unroll
        for (int ri = 0; ri < 4; ++ri) {
            float sv = s[ri];
            sv += __shfl_xor_sync(0xFFFFFFFFu, sv, 1);
            sv += __shfl_xor_sync(0xFFFFFFFFu, sv, 2);
            if ((lane & 3) == 0) {
                int r = rb + wr * 32 + (ri >> 1) * 16 + (ri & 1) * 8 + (lane >> 2);
                g_ps[r][slot] = sv;
            }
        }
        __syncthreads();    // protect smem reuse by next stripe
        tile = tend;
    }
}

// ---------------------------------------------------------------------------
// Kernel 3a/3b: per-row loss and deterministic mean
// loss_row = ln2 * (log2(S - 2^diag) - pos)
// ---------------------------------------------------------------------------
__global__ __launch_bounds__(256) void k_red1()
{
    int t = threadIdx.x;
    int r = blockIdx.x * 256 + t;
    float S = 0.f;
    #pragma unroll
    for (int p = 0; p < PSLOTS; ++p) S += g_ps[r][p];
    S -= ex2f(g_diag[r]);
    float acc = lg2f(S) - g_pos[r];

    #pragma unroll
    for (int o = 16; o > 0; o >>= 1) acc += __shfl_xor_sync(0xFFFFFFFFu, acc, o);
    __shared__ float red[8];
    if ((t & 31) == 0) red[t >> 5] = acc;
    __syncthreads();
    if (t < 8) {
        float v = red[t];
        #pragma unroll
        for (int o = 4; o > 0; o >>= 1) v += __shfl_xor_sync(0xFFu, v, o);
        if (t == 0) g_blk[blockIdx.x] = v;
    }
}

__global__ void k_red2(float* __restrict__ out)
{
    int t = threadIdx.x;   // 32
    float v = g_blk[t];
    #pragma unroll
    for (int o = 16; o > 0; o >>= 1) v += __shfl_xor_sync(0xFFFFFFFFu, v, o);
    if (t == 0) out[0] = v * (LN2f / (float)NROWS);
}

// ---------------------------------------------------------------------------
extern "C" void kernel_launch(void* const* d_in, const int* in_sizes, int n_in,
                              void* d_out, int out_size)
{
    const float* ei = (const float*)d_in[0];
    const float* ej = (const float*)d_in[1];
    float* out = (float*)d_out;
    (void)in_sizes; (void)n_in; (void)out_size;

    cudaFuncSetAttribute(k_main, cudaFuncAttributeMaxDynamicSharedMemorySize,
                         SMEM_TOTAL);

    k_prep<<<BATCH / 8, 256>>>(ei, ej);
    k_main<<<GRID, 256, SMEM_TOTAL>>>();
    k_red1<<<NROWS / 256, 256>>>();
    k_red2<<<1, 32>>>(out);
}

// round 11
// speedup vs baseline: 2.2400x; 2.2400x over previous
#include <cuda_runtime.h>
#include <cstdint>

// ---------------------------------------------------------------- constants
#define BATCH 4096
#define NROWS 8192
#define DIM   256

#define LN2f  0.69314718055994531f
#define C2    2.8853900817779268f            // 2*log2(e)  (1/T * log2 e, T=0.5)
#define SCALE 1.6986442f                     // sqrt(2*log2 e): dot(x,x') = logit in log2 units

#define BM 128                                // rows per stripe
#define BN 32                                 // cols per tile job
#define NSTRIPE (NROWS / BM)                  // 64
#define NCT     (NROWS / BN)                  // 256 col tiles per stripe
#define TT      (NSTRIPE * NCT)               // 16384 tile jobs
#define GRID    296                           // 2 CTAs per SM, exactly
#define PSLOTS  16                            // (CTAs per stripe) x 2 col-halves

#define PITCH   272                           // smem row pitch (256B data + 16B pad)
#define A_BYTES (BM * PITCH)                  // 34816
#define B_BYTES (BN * PITCH)                  // 8704
#define SMEM_A  0
#define SMEM_B0 A_BYTES
#define SMEM_B1 (A_BYTES + B_BYTES)
#define SMEM_TOTAL (A_BYTES + 2 * B_BYTES)    // 52224 -> 2 CTAs/SM

// ------------------------------------------------------------ device scratch
__device__ __align__(16) uint32_t g_q[NROWS * 64];   // e4m3 rows (64 u32 = 256B)
__device__ float g_ps[NROWS][PSLOTS];                // per-row partial exp2 sums
__device__ float g_diag[NROWS];                      // exact fp8 self-logit (log2)
__device__ float g_pos[NROWS];                       // fp32 positive logit (log2)
__device__ float g_blk[32];

// ------------------------------------------------------------- asm helpers
__device__ __forceinline__ uint32_t smem_u32(const void* p) {
    uint32_t a;
    asm("{ .reg .u64 t; cvta.to.shared.u64 t, %1; cvt.u32.u64 %0, t; }" : "=r"(a) : "l"(p));
    return a;
}
__device__ __forceinline__ float ex2f(float x) {
    float y; asm("ex2.approx.ftz.f32 %0, %1;" : "=f"(y) : "f"(x)); return y;
}
__device__ __forceinline__ float lg2f(float x) {
    float y; asm("lg2.approx.f32 %0, %1;" : "=f"(y) : "f"(x)); return y;
}
__device__ __forceinline__ void cp16(uint32_t s, const void* g) {
    asm volatile("cp.async.cg.shared.global [%0], [%1], 16;" :: "r"(s), "l"(g));
}
__device__ __forceinline__ void cp_commit() { asm volatile("cp.async.commit_group;"); }
__device__ __forceinline__ void cp_wait0()  { asm volatile("cp.async.wait_group 0;" ::: "memory"); }
__device__ __forceinline__ void ldmx4(uint32_t* r, uint32_t addr) {
    asm volatile("ldmatrix.sync.aligned.m8n8.x4.shared.b16 {%0,%1,%2,%3}, [%4];"
                 : "=r"(r[0]), "=r"(r[1]), "=r"(r[2]), "=r"(r[3]) : "r"(addr));
}
// FP8 e4m3 MMA, f32 accumulate (plain-target PTX, sm_89+)
__device__ __forceinline__ void mma_fp8(float* c, const uint32_t* a,
                                        uint32_t b0, uint32_t b1) {
    asm volatile("mma.sync.aligned.m16n8k32.row.col.f32.e4m3.e4m3.f32 "
                 "{%0,%1,%2,%3}, {%4,%5,%6,%7}, {%8,%9}, {%0,%1,%2,%3};"
                 : "+f"(c[0]), "+f"(c[1]), "+f"(c[2]), "+f"(c[3])
                 : "r"(a[0]), "r"(a[1]), "r"(a[2]), "r"(a[3]), "r"(b0), "r"(b1));
}
// pack 4 floats -> 4 e4m3 bytes (byte0 = x)
__device__ __forceinline__ uint32_t fp8pack4(float x, float y, float z, float w) {
    uint16_t lo, hi; uint32_t r;
    asm("cvt.rn.satfinite.e4m3x2.f32 %0, %2, %1;" : "=h"(lo) : "f"(x), "f"(y));
    asm("cvt.rn.satfinite.e4m3x2.f32 %0, %2, %1;" : "=h"(hi) : "f"(z), "f"(w));
    asm("mov.b32 %0, {%1, %2};" : "=r"(r) : "h"(lo), "h"(hi));
    return r;
}
// exact dequant: sum of squares of the 4 e4m3 bytes in v
// (e4m3 -> f16 is exact; f16 -> f32 is exact; pure PTX, no half headers)
__device__ __forceinline__ float fp8_sq4(uint32_t v) {
    float f0, f1, f2, f3;
    asm("{ .reg .b16 l, h, a, b, c, d;\n\t"
        "  mov.b32 {l, h}, %4;\n\t"
        "  .reg .b32 p, q;\n\t"
        "  cvt.rn.f16x2.e4m3x2 p, l;\n\t"
        "  cvt.rn.f16x2.e4m3x2 q, h;\n\t"
        "  mov.b32 {a, b}, p;\n\t"
        "  mov.b32 {c, d}, q;\n\t"
        "  cvt.f32.f16 %0, a;\n\t"
        "  cvt.f32.f16 %1, b;\n\t"
        "  cvt.f32.f16 %2, c;\n\t"
        "  cvt.f32.f16 %3, d; }"
        : "=f"(f0), "=f"(f1), "=f"(f2), "=f"(f3) : "r"(v));
    return f0*f0 + f1*f1 + f2*f2 + f3*f3;
}

// ---------------------------------------------------------------------------
// Kernel 1 (prep): one warp per pair (r, r+B).
//  - fp32 norms + cross dot  -> exact positive logit (log2 domain)
//  - e4m3 quantization of both normalized*SCALE rows
//  - exact fp8 self-dot -> diagonal logit matching the MMA
//  - zero the partial-sum slots
// ---------------------------------------------------------------------------
__global__ __launch_bounds__(256) void k_prep(const float* __restrict__ ei,
                                              const float* __restrict__ ej)
{
    int w = threadIdx.x >> 5, lane = threadIdx.x & 31;
    int r = blockIdx.x * 8 + w;                 // 0..4095

    // zero g_ps: 8192*16 = 131072 floats = exactly grid threads
    ((float*)g_ps)[blockIdx.x * 256 + threadIdx.x] = 0.f;

    const float4* A4 = (const float4*)(ei + (size_t)r * DIM);
    const float4* B4 = (const float4*)(ej + (size_t)r * DIM);
    float4 a0 = A4[lane], a1 = A4[lane + 32];
    float4 b0 = B4[lane], b1 = B4[lane + 32];

    float na = a0.x*a0.x + a0.y*a0.y + a0.z*a0.z + a0.w*a0.w
             + a1.x*a1.x + a1.y*a1.y + a1.z*a1.z + a1.w*a1.w;
    float nb = b0.x*b0.x + b0.y*b0.y + b0.z*b0.z + b0.w*b0.w
             + b1.x*b1.x + b1.y*b1.y + b1.z*b1.z + b1.w*b1.w;
    float ab = a0.x*b0.x + a0.y*b0.y + a0.z*b0.z + a0.w*b0.w
             + a1.x*b1.x + a1.y*b1.y + a1.z*b1.z + a1.w*b1.w;
    #pragma unroll
    for (int o = 16; o > 0; o >>= 1) {
        na += __shfl_xor_sync(0xFFFFFFFFu, na, o);
        nb += __shfl_xor_sync(0xFFFFFFFFu, nb, o);
        ab += __shfl_xor_sync(0xFFFFFFFFu, ab, o);
    }
    float inva = rsqrtf(na) * SCALE;
    float invb = rsqrtf(nb) * SCALE;

    uint32_t qa0 = fp8pack4(a0.x*inva, a0.y*inva, a0.z*inva, a0.w*inva);
    uint32_t qa1 = fp8pack4(a1.x*inva, a1.y*inva, a1.z*inva, a1.w*inva);
    uint32_t qb0 = fp8pack4(b0.x*invb, b0.y*invb, b0.z*invb, b0.w*invb);
    uint32_t qb1 = fp8pack4(b1.x*invb, b1.y*invb, b1.z*invb, b1.w*invb);

    g_q[(size_t)r * 64 + lane]                    = qa0;
    g_q[(size_t)r * 64 + lane + 32]               = qa1;
    g_q[(size_t)(r + BATCH) * 64 + lane]          = qb0;
    g_q[(size_t)(r + BATCH) * 64 + lane + 32]     = qb1;

    float fda = fp8_sq4(qa0) + fp8_sq4(qa1);
    float fdb = fp8_sq4(qb0) + fp8_sq4(qb1);
    #pragma unroll
    for (int o = 16; o > 0; o >>= 1) {
        fda += __shfl_xor_sync(0xFFFFFFFFu, fda, o);
        fdb += __shfl_xor_sync(0xFFFFFFFFu, fdb, o);
    }
    if (lane == 0) {
        float pos = C2 * ab * rsqrtf(na * nb);
        g_pos[r] = pos;
        g_pos[r + BATCH] = pos;
        g_diag[r]         = fda;
        g_diag[r + BATCH] = fdb;
    }
}

// ---------------------------------------------------------------------------
// Kernel 2: persistent fp8 e4m3 MMA z z^T + exp2-sum.
// 296 CTAs, each a contiguous range of the 16384 (stripe, 32-col) tile jobs.
// 8 warps = 4 row x 2 col; warp tile 32m x 16n; K=256 in 8 k32 steps.
// ---------------------------------------------------------------------------
__global__ __launch_bounds__(256, 2) void k_main()
{
    extern __shared__ char sm[];
    const uint32_t sb = smem_u32(sm);
    const int t = threadIdx.x, lane = t & 31, wid = t >> 5;
    const int wr = wid >> 1, wc = wid & 1;
    const int c = blockIdx.x;

    const int t0 = (int)(((long long)c * TT) / GRID);
    const int t1 = (int)(((long long)(c + 1) * TT) / GRID);

    // ldmatrix source addresses (b16 view of fp8 tiles)
    const uint32_t a_addr0 = sb + SMEM_A
        + (uint32_t)((wr * 32 + (lane & 15)) * PITCH) + (uint32_t)((lane >> 4) * 16);
    const uint32_t a_addr1 = a_addr0 + 16 * PITCH;
    const uint32_t b_off = (uint32_t)((wc * 16 + ((lane >> 4) << 3) + (lane & 7)) * PITCH)
                         + (uint32_t)(((lane >> 3) & 1) * 16);

    int tile = t0;
    while (tile < t1) {
        const int stripe = tile >> 8;
        const int tend = min(t1, (stripe + 1) << 8);
        const int rb = stripe * BM;
        // CTA that CONTAINS the stripe's first tile anchors slot numbering;
        // each warp column-half gets its own slot.
        const int cown = (int)((((long long)(stripe << 8) + 1) * GRID - 1) / TT);
        const int slot = (c - cown) * 2 + wc;    // 0..11 (< PSLOTS)

        // load A stripe + first B tile (column tile = job index mod NCT)
        {
            const char* ga = (const char*)g_q + (size_t)rb * 256;
            #pragma unroll
            for (int it = 0; it < 8; ++it) {
                int idx = t + it * 256;
                int row = idx >> 4, ck = idx & 15;
                cp16(sb + SMEM_A + row * PITCH + ck * 16, ga + row * 256 + ck * 16);
            }
            const char* gb = (const char*)g_q
                           + (size_t)(tile & (NCT - 1)) * BN * 256;
            #pragma unroll
            for (int it = 0; it < 2; ++it) {
                int idx = t + it * 256;
                int row = idx >> 4, ck = idx & 15;
                cp16(sb + SMEM_B0 + row * PITCH + ck * 16, gb + row * 256 + ck * 16);
            }
            cp_commit(); cp_wait0(); __syncthreads();
        }

        float s[4] = {0.f, 0.f, 0.f, 0.f};

        #pragma unroll 1
        for (int tt = tile; tt < tend; ++tt) {
            const int ib = (tt - tile) & 1;
            const uint32_t bbase = sb + (ib ? SMEM_B1 : SMEM_B0);

            if (tt + 1 < tend) {
                const char* gb = (const char*)g_q
                               + (size_t)((tt + 1) & (NCT - 1)) * BN * 256;
                const uint32_t bdst = sb + (ib ? SMEM_B0 : SMEM_B1);
                #pragma unroll
                for (int it = 0; it < 2; ++it) {
                    int idx = t + it * 256;
                    int row = idx >> 4, ck = idx & 15;
                    cp16(bdst + row * PITCH + ck * 16, gb + row * 256 + ck * 16);
                }
                cp_commit();
            }

            float acc[2][2][4];
            #pragma unroll
            for (int mb = 0; mb < 2; ++mb)
                #pragma unroll
                for (int nb = 0; nb < 2; ++nb)
                    #pragma unroll
                    for (int e = 0; e < 4; ++e) acc[mb][nb][e] = 0.f;

            #pragma unroll
            for (int ks = 0; ks < 8; ++ks) {
                uint32_t af0[4], af1[4], bf[4];
                ldmx4(af0, a_addr0 + ks * 32);
                ldmx4(af1, a_addr1 + ks * 32);
                ldmx4(bf, bbase + b_off + ks * 32);
                mma_fp8(acc[0][0], af0, bf[0], bf[1]);
                mma_fp8(acc[0][1], af0, bf[2], bf[3]);
                mma_fp8(acc[1][0], af1, bf[0], bf[1]);
                mma_fp8(acc[1][1], af1, bf[2], bf[3]);
            }

            // logits are already log2-domain: s += 2^u (diag/pos analytic)
            #pragma unroll
            for (int mb = 0; mb < 2; ++mb)
                #pragma unroll
                for (int nb = 0; nb < 2; ++nb)
                    #pragma unroll
                    for (int e = 0; e < 4; ++e)
                        s[mb * 2 + (e >> 1)] += ex2f(acc[mb][nb][e]);

            if (tt + 1 < tend) { cp_wait0(); __syncthreads(); }
        }

        // flush row partials: 4 lanes share each row
        #pragma unroll
        for (int ri = 0; ri < 4; ++ri) {
            float sv = s[ri];
            sv += __shfl_xor_sync(0xFFFFFFFFu, sv, 1);
            sv += __shfl_xor_sync(0xFFFFFFFFu, sv, 2);
            if ((lane & 3) == 0) {
                int r = rb + wr * 32 + (ri >> 1) * 16 + (ri & 1) * 8 + (lane >> 2);
                g_ps[r][slot] = sv;
            }
        }
        __syncthreads();    // protect smem reuse by next stripe
        tile = tend;
    }
}

// ---------------------------------------------------------------------------
// Kernel 3a/3b: per-row loss and deterministic mean
// loss_row = ln2 * (log2(S - 2^diag) - pos)
// ---------------------------------------------------------------------------
__global__ __launch_bounds__(256) void k_red1()
{
    int t = threadIdx.x;
    int r = blockIdx.x * 256 + t;
    float S = 0.f;
    #pragma unroll
    for (int p = 0; p < PSLOTS; ++p) S += g_ps[r][p];
    S -= ex2f(g_diag[r]);
    float acc = lg2f(S) - g_pos[r];

    #pragma unroll
    for (int o = 16; o > 0; o >>= 1) acc += __shfl_xor_sync(0xFFFFFFFFu, acc, o);
    __shared__ float red[8];
    if ((t & 31) == 0) red[t >> 5] = acc;
    __syncthreads();
    if (t < 8) {
        float v = red[t];
        #pragma unroll
        for (int o = 4; o > 0; o >>= 1) v += __shfl_xor_sync(0xFFu, v, o);
        if (t == 0) g_blk[blockIdx.x] = v;
    }
}

__global__ void k_red2(float* __restrict__ out)
{
    int t = threadIdx.x;   // 32
    float v = g_blk[t];
    #pragma unroll
    for (int o = 16; o > 0; o >>= 1) v += __shfl_xor_sync(0xFFFFFFFFu, v, o);
    if (t == 0) out[0] = v * (LN2f / (float)NROWS);
}

// ---------------------------------------------------------------------------
extern "C" void kernel_launch(void* const* d_in, const int* in_sizes, int n_in,
                              void* d_out, int out_size)
{
    const float* ei = (const float*)d_in[0];
    const float* ej = (const float*)d_in[1];
    float* out = (float*)d_out;
    (void)in_sizes; (void)n_in; (void)out_size;

    cudaFuncSetAttribute(k_main, cudaFuncAttributeMaxDynamicSharedMemorySize,
                         SMEM_TOTAL);

    k_prep<<<BATCH / 8, 256>>>(ei, ej);
    k_main<<<GRID, 256, SMEM_TOTAL>>>();
    k_red1<<<NROWS / 256, 256>>>();
    k_red2<<<1, 32>>>(out);
}

// round 12
// speedup vs baseline: 2.3239x; 1.0375x over previous
#include <cuda_runtime.h>
#include <cstdint>

// ---------------------------------------------------------------- constants
#define BATCH 4096
#define NROWS 8192
#define DIM   256

#define LN2f  0.69314718055994531f
#define C2    2.8853900817779268f            // 2*log2(e)  (1/T * log2 e, T=0.5)
#define SCALE 1.6986442f                     // sqrt(2*log2 e): dot(x,x') = logit in log2 units

#define BM 128                                // rows per stripe
#define BN 32                                 // cols per tile job
#define NSTRIPE (NROWS / BM)                  // 64
#define NCT     (NROWS / BN)                  // 256 col tiles per stripe
#define TT      (NSTRIPE * NCT)               // 16384 tile jobs
#define GRID    296                           // 2 CTAs per SM, exactly
#define PSLOTS  16                            // (CTAs per stripe) x 2 col-halves

#define PITCH   272                           // smem row pitch (256B data + 16B pad)
#define A_BYTES (BM * PITCH)                  // 34816
#define B_BYTES (BN * PITCH)                  // 8704
#define SMEM_A  0
#define SMEM_B0 A_BYTES
#define SMEM_B1 (A_BYTES + B_BYTES)
#define SMEM_TOTAL (A_BYTES + 2 * B_BYTES)    // 52224 -> 2 CTAs/SM

#define RBLK 32                               // reduce blocks

// ------------------------------------------------------------ device scratch
__device__ __align__(16) uint32_t g_q[NROWS * 64];   // e4m3 rows (64 u32 = 256B)
__device__ __align__(16) float g_ps[NROWS][PSLOTS];  // per-row partial exp2 sums
__device__ float g_diag[NROWS];                      // exact fp8 self-logit (log2)
__device__ float g_pos[NROWS];                       // fp32 positive logit (log2)
__device__ float g_blk[RBLK];
__device__ unsigned g_cnt;

// ------------------------------------------------------------- asm helpers
__device__ __forceinline__ uint32_t smem_u32(const void* p) {
    uint32_t a;
    asm("{ .reg .u64 t; cvta.to.shared.u64 t, %1; cvt.u32.u64 %0, t; }" : "=r"(a) : "l"(p));
    return a;
}
__device__ __forceinline__ float ex2f(float x) {
    float y; asm("ex2.approx.ftz.f32 %0, %1;" : "=f"(y) : "f"(x)); return y;
}
__device__ __forceinline__ float lg2f(float x) {
    float y; asm("lg2.approx.f32 %0, %1;" : "=f"(y) : "f"(x)); return y;
}
__device__ __forceinline__ void cp16(uint32_t s, const void* g) {
    asm volatile("cp.async.cg.shared.global [%0], [%1], 16;" :: "r"(s), "l"(g));
}
__device__ __forceinline__ void cp_commit() { asm volatile("cp.async.commit_group;"); }
__device__ __forceinline__ void cp_wait0()  { asm volatile("cp.async.wait_group 0;" ::: "memory"); }
__device__ __forceinline__ void ldmx4(uint32_t* r, uint32_t addr) {
    asm volatile("ldmatrix.sync.aligned.m8n8.x4.shared.b16 {%0,%1,%2,%3}, [%4];"
                 : "=r"(r[0]), "=r"(r[1]), "=r"(r[2]), "=r"(r[3]) : "r"(addr));
}
// FP8 e4m3 MMA, f32 accumulate (plain-target PTX, sm_89+)
__device__ __forceinline__ void mma_fp8(float* c, const uint32_t* a,
                                        uint32_t b0, uint32_t b1) {
    asm volatile("mma.sync.aligned.m16n8k32.row.col.f32.e4m3.e4m3.f32 "
                 "{%0,%1,%2,%3}, {%4,%5,%6,%7}, {%8,%9}, {%0,%1,%2,%3};"
                 : "+f"(c[0]), "+f"(c[1]), "+f"(c[2]), "+f"(c[3])
                 : "r"(a[0]), "r"(a[1]), "r"(a[2]), "r"(a[3]), "r"(b0), "r"(b1));
}
// pack 4 floats -> 4 e4m3 bytes (byte0 = x)
__device__ __forceinline__ uint32_t fp8pack4(float x, float y, float z, float w) {
    uint16_t lo, hi; uint32_t r;
    asm("cvt.rn.satfinite.e4m3x2.f32 %0, %2, %1;" : "=h"(lo) : "f"(x), "f"(y));
    asm("cvt.rn.satfinite.e4m3x2.f32 %0, %2, %1;" : "=h"(hi) : "f"(z), "f"(w));
    asm("mov.b32 %0, {%1, %2};" : "=r"(r) : "h"(lo), "h"(hi));
    return r;
}
// exact dequant: sum of squares of the 4 e4m3 bytes in v (pure PTX)
__device__ __forceinline__ float fp8_sq4(uint32_t v) {
    float f0, f1, f2, f3;
    asm("{ .reg .b16 l, h, a, b, c, d;\n\t"
        "  mov.b32 {l, h}, %4;\n\t"
        "  .reg .b32 p, q;\n\t"
        "  cvt.rn.f16x2.e4m3x2 p, l;\n\t"
        "  cvt.rn.f16x2.e4m3x2 q, h;\n\t"
        "  mov.b32 {a, b}, p;\n\t"
        "  mov.b32 {c, d}, q;\n\t"
        "  cvt.f32.f16 %0, a;\n\t"
        "  cvt.f32.f16 %1, b;\n\t"
        "  cvt.f32.f16 %2, c;\n\t"
        "  cvt.f32.f16 %3, d; }"
        : "=f"(f0), "=f"(f1), "=f"(f2), "=f"(f3) : "r"(v));
    return f0*f0 + f1*f1 + f2*f2 + f3*f3;
}

// ---------------------------------------------------------------------------
// Kernel 1 (prep): one warp per pair (r, r+B). (unchanged from R11)
// ---------------------------------------------------------------------------
__global__ __launch_bounds__(256) void k_prep(const float* __restrict__ ei,
                                              const float* __restrict__ ej)
{
    int w = threadIdx.x >> 5, lane = threadIdx.x & 31;
    int r = blockIdx.x * 8 + w;                 // 0..4095

    int gid = blockIdx.x * 256 + threadIdx.x;
    ((float*)g_ps)[gid] = 0.f;                  // 8192*16 = exactly grid threads
    if (gid == 0) g_cnt = 0;

    const float4* A4 = (const float4*)(ei + (size_t)r * DIM);
    const float4* B4 = (const float4*)(ej + (size_t)r * DIM);
    float4 a0 = A4[lane], a1 = A4[lane + 32];
    float4 b0 = B4[lane], b1 = B4[lane + 32];

    float na = a0.x*a0.x + a0.y*a0.y + a0.z*a0.z + a0.w*a0.w
             + a1.x*a1.x + a1.y*a1.y + a1.z*a1.z + a1.w*a1.w;
    float nb = b0.x*b0.x + b0.y*b0.y + b0.z*b0.z + b0.w*b0.w
             + b1.x*b1.x + b1.y*b1.y + b1.z*b1.z + b1.w*b1.w;
    float ab = a0.x*b0.x + a0.y*b0.y + a0.z*b0.z + a0.w*b0.w
             + a1.x*b1.x + a1.y*b1.y + a1.z*b1.z + a1.w*b1.w;
    #pragma unroll
    for (int o = 16; o > 0; o >>= 1) {
        na += __shfl_xor_sync(0xFFFFFFFFu, na, o);
        nb += __shfl_xor_sync(0xFFFFFFFFu, nb, o);
        ab += __shfl_xor_sync(0xFFFFFFFFu, ab, o);
    }
    float inva = rsqrtf(na) * SCALE;
    float invb = rsqrtf(nb) * SCALE;

    uint32_t qa0 = fp8pack4(a0.x*inva, a0.y*inva, a0.z*inva, a0.w*inva);
    uint32_t qa1 = fp8pack4(a1.x*inva, a1.y*inva, a1.z*inva, a1.w*inva);
    uint32_t qb0 = fp8pack4(b0.x*invb, b0.y*invb, b0.z*invb, b0.w*invb);
    uint32_t qb1 = fp8pack4(b1.x*invb, b1.y*invb, b1.z*invb, b1.w*invb);

    g_q[(size_t)r * 64 + lane]                    = qa0;
    g_q[(size_t)r * 64 + lane + 32]               = qa1;
    g_q[(size_t)(r + BATCH) * 64 + lane]          = qb0;
    g_q[(size_t)(r + BATCH) * 64 + lane + 32]     = qb1;

    float fda = fp8_sq4(qa0) + fp8_sq4(qa1);
    float fdb = fp8_sq4(qb0) + fp8_sq4(qb1);
    #pragma unroll
    for (int o = 16; o > 0; o >>= 1) {
        fda += __shfl_xor_sync(0xFFFFFFFFu, fda, o);
        fdb += __shfl_xor_sync(0xFFFFFFFFu, fdb, o);
    }
    if (lane == 0) {
        float pos = C2 * ab * rsqrtf(na * nb);
        g_pos[r] = pos;
        g_pos[r + BATCH] = pos;
        g_diag[r]         = fda;
        g_diag[r + BATCH] = fdb;
    }
}

// ---------------------------------------------------------------------------
// Tile step: MMA tile tt into accC; if EPI, interleave epilogue of accP
// (2 elements per k-step). Epilogue is position-independent (pure 2^u sum),
// so deferring it one tile is exact.
// acc linear layout: L = mb*8 + nb*4 + e  ->  s index (L>>3)*2 + ((L&3)>>1)
// ---------------------------------------------------------------------------
template <bool EPI>
__device__ __forceinline__ void tile_step(
    int tt, int tile, int tend, int t, uint32_t sb,
    uint32_t a_addr0, uint32_t a_addr1, uint32_t b_off,
    float* accC, float* accP, float* s)
{
    const int ib = (tt - tile) & 1;
    const uint32_t bbase = sb + (ib ? SMEM_B1 : SMEM_B0);
    const bool pf = (tt + 1 < tend);

    if (pf) {
        const char* gb = (const char*)g_q + (size_t)((tt + 1) & (NCT - 1)) * BN * 256;
        const uint32_t bdst = sb + (ib ? SMEM_B0 : SMEM_B1);
        #pragma unroll
        for (int it = 0; it < 2; ++it) {
            int idx = t + it * 256;
            int row = idx >> 4, ck = idx & 15;
            cp16(bdst + row * PITCH + ck * 16, gb + row * 256 + ck * 16);
        }
        cp_commit();
    }

    #pragma unroll
    for (int e = 0; e < 16; ++e) accC[e] = 0.f;

    #pragma unroll
    for (int ks = 0; ks < 8; ++ks) {
        uint32_t af0[4], af1[4], bf[4];
        ldmx4(af0, a_addr0 + ks * 32);
        ldmx4(af1, a_addr1 + ks * 32);
        ldmx4(bf, bbase + b_off + ks * 32);
        mma_fp8(accC + 0,  af0, bf[0], bf[1]);
        mma_fp8(accC + 4,  af0, bf[2], bf[3]);
        mma_fp8(accC + 8,  af1, bf[0], bf[1]);
        mma_fp8(accC + 12, af1, bf[2], bf[3]);
        if (EPI) {
            const int L0 = ks * 2, L1 = ks * 2 + 1;
            s[(L0 >> 3) * 2 + ((L0 & 3) >> 1)] += ex2f(accP[L0]);
            s[(L1 >> 3) * 2 + ((L1 & 3) >> 1)] += ex2f(accP[L1]);
        }
    }

    if (pf) { cp_wait0(); __syncthreads(); }
}

__device__ __forceinline__ void epi_all(const float* acc, float* s)
{
    #pragma unroll
    for (int L = 0; L < 16; ++L)
        s[(L >> 3) * 2 + ((L & 3) >> 1)] += ex2f(acc[L]);
}

// ---------------------------------------------------------------------------
// Kernel 2: persistent fp8 e4m3 MMA z z^T + deferred exp2-sum epilogue.
// ---------------------------------------------------------------------------
__global__ __launch_bounds__(256, 2) void k_main()
{
    extern __shared__ char sm[];
    const uint32_t sb = smem_u32(sm);
    const int t = threadIdx.x, lane = t & 31, wid = t >> 5;
    const int wr = wid >> 1, wc = wid & 1;
    const int c = blockIdx.x;

    const int t0 = (int)(((long long)c * TT) / GRID);
    const int t1 = (int)(((long long)(c + 1) * TT) / GRID);

    const uint32_t a_addr0 = sb + SMEM_A
        + (uint32_t)((wr * 32 + (lane & 15)) * PITCH) + (uint32_t)((lane >> 4) * 16);
    const uint32_t a_addr1 = a_addr0 + 16 * PITCH;
    const uint32_t b_off = (uint32_t)((wc * 16 + ((lane >> 4) << 3) + (lane & 7)) * PITCH)
                         + (uint32_t)(((lane >> 3) & 1) * 16);

    int tile = t0;
    while (tile < t1) {
        const int stripe = tile >> 8;
        const int tend = min(t1, (stripe + 1) << 8);
        const int rb = stripe * BM;
        const int cown = (int)((((long long)(stripe << 8) + 1) * GRID - 1) / TT);
        const int slot = (c - cown) * 2 + wc;    // 0..11 (< PSLOTS)

        // load A stripe + first B tile
        {
            const char* ga = (const char*)g_q + (size_t)rb * 256;
            #pragma unroll
            for (int it = 0; it < 8; ++it) {
                int idx = t + it * 256;
                int row = idx >> 4, ck = idx & 15;
                cp16(sb + SMEM_A + row * PITCH + ck * 16, ga + row * 256 + ck * 16);
            }
            const char* gb = (const char*)g_q + (size_t)(tile & (NCT - 1)) * BN * 256;
            #pragma unroll
            for (int it = 0; it < 2; ++it) {
                int idx = t + it * 256;
                int row = idx >> 4, ck = idx & 15;
                cp16(sb + SMEM_B0 + row * PITCH + ck * 16, gb + row * 256 + ck * 16);
            }
            cp_commit(); cp_wait0(); __syncthreads();
        }

        float s[4] = {0.f, 0.f, 0.f, 0.f};
        float acc0[16], acc1[16];
        const int n = tend - tile;

        // software pipeline: tile i's MMA overlaps tile i-1's epilogue
        tile_step<false>(tile, tile, tend, t, sb, a_addr0, a_addr1, b_off,
                         acc0, acc1, s);
        int k = 1;
        for (; k + 1 < n; k += 2) {
            tile_step<true>(tile + k,     tile, tend, t, sb, a_addr0, a_addr1,
                            b_off, acc1, acc0, s);
            tile_step<true>(tile + k + 1, tile, tend, t, sb, a_addr0, a_addr1,
                            b_off, acc0, acc1, s);
        }
        if (k < n) {
            tile_step<true>(tile + k, tile, tend, t, sb, a_addr0, a_addr1,
                            b_off, acc1, acc0, s);
            epi_all(acc1, s);
        } else {
            epi_all(acc0, s);
        }

        // flush row partials: 4 lanes share each row
        #pragma unroll
        for (int ri = 0; ri < 4; ++ri) {
            float sv = s[ri];
            sv += __shfl_xor_sync(0xFFFFFFFFu, sv, 1);
            sv += __shfl_xor_sync(0xFFFFFFFFu, sv, 2);
            if ((lane & 3) == 0) {
                int r = rb + wr * 32 + (ri >> 1) * 16 + (ri & 1) * 8 + (lane >> 2);
                g_ps[r][slot] = sv;
            }
        }
        __syncthreads();    // protect smem reuse by next stripe
        tile = tend;
    }
}

// ---------------------------------------------------------------------------
// Kernel 3: per-row loss + fused deterministic mean (last-block reduction)
// loss_row = ln2 * (log2(S - 2^diag) - pos)
// ---------------------------------------------------------------------------
__global__ __launch_bounds__(256) void k_red(float* __restrict__ out)
{
    int t = threadIdx.x;
    int r = blockIdx.x * 256 + t;

    const float4* p4 = (const float4*)g_ps[r];
    float4 v0 = p4[0], v1 = p4[1], v2 = p4[2], v3 = p4[3];
    float S = ((v0.x + v0.y) + (v0.z + v0.w)) + ((v1.x + v1.y) + (v1.z + v1.w))
            + ((v2.x + v2.y) + (v2.z + v2.w)) + ((v3.x + v3.y) + (v3.z + v3.w));
    S -= ex2f(g_diag[r]);
    float acc = lg2f(S) - g_pos[r];

    #pragma unroll
    for (int o = 16; o > 0; o >>= 1) acc += __shfl_xor_sync(0xFFFFFFFFu, acc, o);
    __shared__ float red[8];
    __shared__ unsigned rank;
    if ((t & 31) == 0) red[t >> 5] = acc;
    __syncthreads();
    if (t < 8) {
        float v = red[t];
        #pragma unroll
        for (int o = 4; o > 0; o >>= 1) v += __shfl_xor_sync(0xFFu, v, o);
        if (t == 0) {
            g_blk[blockIdx.x] = v;
            __threadfence();
            rank = atomicAdd(&g_cnt, 1u);
        }
    }
    __syncthreads();
    if (rank == RBLK - 1 && t < RBLK) {   // last block finishes the mean
        float v = *((volatile float*)&g_blk[t]);
        #pragma unroll
        for (int o = 16; o > 0; o >>= 1) v += __shfl_xor_sync(0xFFFFFFFFu, v, o);
        if (t == 0) out[0] = v * (LN2f / (float)NROWS);
    }
}

// ---------------------------------------------------------------------------
extern "C" void kernel_launch(void* const* d_in, const int* in_sizes, int n_in,
                              void* d_out, int out_size)
{
    const float* ei = (const float*)d_in[0];
    const float* ej = (const float*)d_in[1];
    float* out = (float*)d_out;
    (void)in_sizes; (void)n_in; (void)out_size;

    cudaFuncSetAttribute(k_main, cudaFuncAttributeMaxDynamicSharedMemorySize,
                         SMEM_TOTAL);

    k_prep<<<BATCH / 8, 256>>>(ei, ej);
    k_main<<<GRID, 256, SMEM_TOTAL>>>();
    k_red<<<RBLK, 256>>>(out);
}

// round 13
// speedup vs baseline: 2.4114x; 1.0376x over previous
#include <cuda_runtime.h>
#include <cstdint>

// ---------------------------------------------------------------- constants
#define BATCH 4096
#define NROWS 8192
#define DIM   256

#define LN2f  0.69314718055994531f
#define C2    2.8853900817779268f            // 2*log2(e)  (1/T * log2 e, T=0.5)
#define SCALE 1.6986442f                     // sqrt(2*log2 e)

#define BM 128                                // rows per stripe
#define BN 64                                 // cols per tile job
#define NSTRIPE (NROWS / BM)                  // 64
#define NCT     (NROWS / BN)                  // 128 col tiles per stripe
#define TT      (NSTRIPE * NCT)               // 8192 tile jobs
#define GRID    296                           // 2 CTAs per SM, exactly
#define PSLOTS  16                            // (CTAs per stripe) x 2 col-halves

#define PITCH   272                           // smem row pitch (256B data + 16B pad)
#define A_BYTES (BM * PITCH)                  // 34816
#define B_BYTES (BN * PITCH)                  // 17408
#define SMEM_A  0
#define SMEM_B0 A_BYTES
#define SMEM_B1 (A_BYTES + B_BYTES)
#define SMEM_TOTAL (A_BYTES + 2 * B_BYTES)    // 69632 -> 2 CTAs/SM

#define RBLK 32                               // reduce blocks

// ------------------------------------------------------------ device scratch
__device__ __align__(16) uint32_t g_q[NROWS * 64];   // e4m3 rows (64 u32 = 256B)
__device__ __align__(16) float g_ps[NROWS][PSLOTS];  // per-row partial exp2 sums
__device__ float g_diag[NROWS];                      // exact fp8 self-logit (log2)
__device__ float g_pos[NROWS];                       // fp32 positive logit (log2)
__device__ float g_blk[RBLK];
__device__ unsigned g_cnt;

// ------------------------------------------------------------- asm helpers
__device__ __forceinline__ uint32_t smem_u32(const void* p) {
    uint32_t a;
    asm("{ .reg .u64 t; cvta.to.shared.u64 t, %1; cvt.u32.u64 %0, t; }" : "=r"(a) : "l"(p));
    return a;
}
__device__ __forceinline__ float ex2f(float x) {
    float y; asm("ex2.approx.ftz.f32 %0, %1;" : "=f"(y) : "f"(x)); return y;
}
__device__ __forceinline__ float lg2f(float x) {
    float y; asm("lg2.approx.f32 %0, %1;" : "=f"(y) : "f"(x)); return y;
}
__device__ __forceinline__ void cp16(uint32_t s, const void* g) {
    asm volatile("cp.async.cg.shared.global [%0], [%1], 16;" :: "r"(s), "l"(g));
}
__device__ __forceinline__ void cp_commit() { asm volatile("cp.async.commit_group;"); }
__device__ __forceinline__ void cp_wait0()  { asm volatile("cp.async.wait_group 0;" ::: "memory"); }
__device__ __forceinline__ void ldmx4(uint32_t* r, uint32_t addr) {
    asm volatile("ldmatrix.sync.aligned.m8n8.x4.shared.b16 {%0,%1,%2,%3}, [%4];"
                 : "=r"(r[0]), "=r"(r[1]), "=r"(r[2]), "=r"(r[3]) : "r"(addr));
}
// FP8 e4m3 MMA, f32 accumulate (plain-target PTX, sm_89+)
__device__ __forceinline__ void mma_fp8(float* c, const uint32_t* a,
                                        uint32_t b0, uint32_t b1) {
    asm volatile("mma.sync.aligned.m16n8k32.row.col.f32.e4m3.e4m3.f32 "
                 "{%0,%1,%2,%3}, {%4,%5,%6,%7}, {%8,%9}, {%0,%1,%2,%3};"
                 : "+f"(c[0]), "+f"(c[1]), "+f"(c[2]), "+f"(c[3])
                 : "r"(a[0]), "r"(a[1]), "r"(a[2]), "r"(a[3]), "r"(b0), "r"(b1));
}
// pack 4 floats -> 4 e4m3 bytes (byte0 = x)
__device__ __forceinline__ uint32_t fp8pack4(float x, float y, float z, float w) {
    uint16_t lo, hi; uint32_t r;
    asm("cvt.rn.satfinite.e4m3x2.f32 %0, %2, %1;" : "=h"(lo) : "f"(x), "f"(y));
    asm("cvt.rn.satfinite.e4m3x2.f32 %0, %2, %1;" : "=h"(hi) : "f"(z), "f"(w));
    asm("mov.b32 %0, {%1, %2};" : "=r"(r) : "h"(lo), "h"(hi));
    return r;
}
// exact dequant: sum of squares of the 4 e4m3 bytes in v (pure PTX)
__device__ __forceinline__ float fp8_sq4(uint32_t v) {
    float f0, f1, f2, f3;
    asm("{ .reg .b16 l, h, a, b, c, d;\n\t"
        "  mov.b32 {l, h}, %4;\n\t"
        "  .reg .b32 p, q;\n\t"
        "  cvt.rn.f16x2.e4m3x2 p, l;\n\t"
        "  cvt.rn.f16x2.e4m3x2 q, h;\n\t"
        "  mov.b32 {a, b}, p;\n\t"
        "  mov.b32 {c, d}, q;\n\t"
        "  cvt.f32.f16 %0, a;\n\t"
        "  cvt.f32.f16 %1, b;\n\t"
        "  cvt.f32.f16 %2, c;\n\t"
        "  cvt.f32.f16 %3, d; }"
        : "=f"(f0), "=f"(f1), "=f"(f2), "=f"(f3) : "r"(v));
    return f0*f0 + f1*f1 + f2*f2 + f3*f3;
}

// ---------------------------------------------------------------------------
// Kernel 1 (prep): one warp per pair (r, r+B). (unchanged)
// ---------------------------------------------------------------------------
__global__ __launch_bounds__(256) void k_prep(const float* __restrict__ ei,
                                              const float* __restrict__ ej)
{
    int w = threadIdx.x >> 5, lane = threadIdx.x & 31;
    int r = blockIdx.x * 8 + w;                 // 0..4095

    int gid = blockIdx.x * 256 + threadIdx.x;
    ((float*)g_ps)[gid] = 0.f;                  // 8192*16 = exactly grid threads
    if (gid == 0) g_cnt = 0;

    const float4* A4 = (const float4*)(ei + (size_t)r * DIM);
    const float4* B4 = (const float4*)(ej + (size_t)r * DIM);
    float4 a0 = A4[lane], a1 = A4[lane + 32];
    float4 b0 = B4[lane], b1 = B4[lane + 32];

    float na = a0.x*a0.x + a0.y*a0.y + a0.z*a0.z + a0.w*a0.w
             + a1.x*a1.x + a1.y*a1.y + a1.z*a1.z + a1.w*a1.w;
    float nb = b0.x*b0.x + b0.y*b0.y + b0.z*b0.z + b0.w*b0.w
             + b1.x*b1.x + b1.y*b1.y + b1.z*b1.z + b1.w*b1.w;
    float ab = a0.x*b0.x + a0.y*b0.y + a0.z*b0.z + a0.w*b0.w
             + a1.x*b1.x + a1.y*b1.y + a1.z*b1.z + a1.w*b1.w;
    #pragma unroll
    for (int o = 16; o > 0; o >>= 1) {
        na += __shfl_xor_sync(0xFFFFFFFFu, na, o);
        nb += __shfl_xor_sync(0xFFFFFFFFu, nb, o);
        ab += __shfl_xor_sync(0xFFFFFFFFu, ab, o);
    }
    float inva = rsqrtf(na) * SCALE;
    float invb = rsqrtf(nb) * SCALE;

    uint32_t qa0 = fp8pack4(a0.x*inva, a0.y*inva, a0.z*inva, a0.w*inva);
    uint32_t qa1 = fp8pack4(a1.x*inva, a1.y*inva, a1.z*inva, a1.w*inva);
    uint32_t qb0 = fp8pack4(b0.x*invb, b0.y*invb, b0.z*invb, b0.w*invb);
    uint32_t qb1 = fp8pack4(b1.x*invb, b1.y*invb, b1.z*invb, b1.w*invb);

    g_q[(size_t)r * 64 + lane]                    = qa0;
    g_q[(size_t)r * 64 + lane + 32]               = qa1;
    g_q[(size_t)(r + BATCH) * 64 + lane]          = qb0;
    g_q[(size_t)(r + BATCH) * 64 + lane + 32]     = qb1;

    float fda = fp8_sq4(qa0) + fp8_sq4(qa1);
    float fdb = fp8_sq4(qb0) + fp8_sq4(qb1);
    #pragma unroll
    for (int o = 16; o > 0; o >>= 1) {
        fda += __shfl_xor_sync(0xFFFFFFFFu, fda, o);
        fdb += __shfl_xor_sync(0xFFFFFFFFu, fdb, o);
    }
    if (lane == 0) {
        float pos = C2 * ab * rsqrtf(na * nb);
        g_pos[r] = pos;
        g_pos[r + BATCH] = pos;
        g_diag[r]         = fda;
        g_diag[r + BATCH] = fdb;
    }
}

// ---------------------------------------------------------------------------
// Tile step: MMA tile tt (128x64) into accC[32]; if EPI, interleave epilogue
// of accP (4 elements per k-step). Epilogue is position-independent.
// acc layout: L = mb*16 + nb*4 + e  ->  s index (L>>4)*2 + ((L&3)>>1)
// ---------------------------------------------------------------------------
template <bool EPI>
__device__ __forceinline__ void tile_step(
    int tt, int tile, int tend, int t, uint32_t sb,
    uint32_t a_addr0, uint32_t a_addr1, uint32_t b_off0, uint32_t b_off1,
    float* accC, float* accP, float* s)
{
    const int ib = (tt - tile) & 1;
    const uint32_t bbase = sb + (ib ? SMEM_B1 : SMEM_B0);
    const bool pf = (tt + 1 < tend);

    if (pf) {
        const char* gb = (const char*)g_q + (size_t)((tt + 1) & (NCT - 1)) * BN * 256;
        const uint32_t bdst = sb + (ib ? SMEM_B0 : SMEM_B1);
        #pragma unroll
        for (int it = 0; it < 4; ++it) {
            int idx = t + it * 256;
            int row = idx >> 4, ck = idx & 15;
            cp16(bdst + row * PITCH + ck * 16, gb + row * 256 + ck * 16);
        }
        cp_commit();
    }

    #pragma unroll
    for (int e = 0; e < 32; ++e) accC[e] = 0.f;

    #pragma unroll
    for (int ks = 0; ks < 8; ++ks) {
        uint32_t af0[4], af1[4], bf0[4], bf1[4];
        ldmx4(af0, a_addr0 + ks * 32);
        ldmx4(af1, a_addr1 + ks * 32);
        ldmx4(bf0, bbase + b_off0 + ks * 32);
        ldmx4(bf1, bbase + b_off1 + ks * 32);
        mma_fp8(accC + 0,  af0, bf0[0], bf0[1]);
        mma_fp8(accC + 4,  af0, bf0[2], bf0[3]);
        mma_fp8(accC + 8,  af0, bf1[0], bf1[1]);
        mma_fp8(accC + 12, af0, bf1[2], bf1[3]);
        mma_fp8(accC + 16, af1, bf0[0], bf0[1]);
        mma_fp8(accC + 20, af1, bf0[2], bf0[3]);
        mma_fp8(accC + 24, af1, bf1[0], bf1[1]);
        mma_fp8(accC + 28, af1, bf1[2], bf1[3]);
        if (EPI) {
            #pragma unroll
            for (int j = 0; j < 4; ++j) {
                const int L = ks * 4 + j;
                s[(L >> 4) * 2 + ((L & 3) >> 1)] += ex2f(accP[L]);
            }
        }
    }

    if (pf) { cp_wait0(); __syncthreads(); }
}

__device__ __forceinline__ void epi_all(const float* acc, float* s)
{
    #pragma unroll
    for (int L = 0; L < 32; ++L)
        s[(L >> 4) * 2 + ((L & 3) >> 1)] += ex2f(acc[L]);
}

// ---------------------------------------------------------------------------
// Kernel 2: persistent fp8 e4m3 MMA z z^T + deferred exp2-sum epilogue.
// 296 CTAs over 8192 (stripe, 64-col) tile jobs.
// 8 warps = 4 row x 2 col; warp tile 32m x 32n; K=256 in 8 k32 steps.
// ---------------------------------------------------------------------------
__global__ __launch_bounds__(256, 2) void k_main()
{
    extern __shared__ char sm[];
    const uint32_t sb = smem_u32(sm);
    const int t = threadIdx.x, lane = t & 31, wid = t >> 5;
    const int wr = wid >> 1, wc = wid & 1;
    const int c = blockIdx.x;

    const int t0 = (int)(((long long)c * TT) / GRID);
    const int t1 = (int)(((long long)(c + 1) * TT) / GRID);

    const uint32_t a_addr0 = sb + SMEM_A
        + (uint32_t)((wr * 32 + (lane & 15)) * PITCH) + (uint32_t)((lane >> 4) * 16);
    const uint32_t a_addr1 = a_addr0 + 16 * PITCH;
    const int nsub = ((lane >> 4) << 3) + (lane & 7);
    const uint32_t bko = (uint32_t)(((lane >> 3) & 1) * 16);
    const uint32_t b_off0 = (uint32_t)((wc * 32 + nsub) * PITCH) + bko;
    const uint32_t b_off1 = (uint32_t)((wc * 32 + 16 + nsub) * PITCH) + bko;

    int tile = t0;
    while (tile < t1) {
        const int stripe = tile >> 7;            // NCT = 128
        const int tend = min(t1, (stripe + 1) << 7);
        const int rb = stripe * BM;
        const int cown = (int)((((long long)(stripe << 7) + 1) * GRID - 1) / TT);
        const int slot = (c - cown) * 2 + wc;    // 0..11 (< PSLOTS)

        // load A stripe + first B tile
        {
            const char* ga = (const char*)g_q + (size_t)rb * 256;
            #pragma unroll
            for (int it = 0; it < 8; ++it) {
                int idx = t + it * 256;
                int row = idx >> 4, ck = idx & 15;
                cp16(sb + SMEM_A + row * PITCH + ck * 16, ga + row * 256 + ck * 16);
            }
            const char* gb = (const char*)g_q + (size_t)(tile & (NCT - 1)) * BN * 256;
            #pragma unroll
            for (int it = 0; it < 4; ++it) {
                int idx = t + it * 256;
                int row = idx >> 4, ck = idx & 15;
                cp16(sb + SMEM_B0 + row * PITCH + ck * 16, gb + row * 256 + ck * 16);
            }
            cp_commit(); cp_wait0(); __syncthreads();
        }

        float s[4] = {0.f, 0.f, 0.f, 0.f};
        float acc0[32], acc1[32];
        const int n = tend - tile;

        // software pipeline: tile i's MMA overlaps tile i-1's epilogue
        tile_step<false>(tile, tile, tend, t, sb, a_addr0, a_addr1,
                         b_off0, b_off1, acc0, acc1, s);
        int k = 1;
        for (; k + 1 < n; k += 2) {
            tile_step<true>(tile + k,     tile, tend, t, sb, a_addr0, a_addr1,
                            b_off0, b_off1, acc1, acc0, s);
            tile_step<true>(tile + k + 1, tile, tend, t, sb, a_addr0, a_addr1,
                            b_off0, b_off1, acc0, acc1, s);
        }
        if (k < n) {
            tile_step<true>(tile + k, tile, tend, t, sb, a_addr0, a_addr1,
                            b_off0, b_off1, acc1, acc0, s);
            epi_all(acc1, s);
        } else {
            epi_all(acc0, s);
        }

        // flush row partials: 4 lanes share each row
        #pragma unroll
        for (int ri = 0; ri < 4; ++ri) {
            float sv = s[ri];
            sv += __shfl_xor_sync(0xFFFFFFFFu, sv, 1);
            sv += __shfl_xor_sync(0xFFFFFFFFu, sv, 2);
            if ((lane & 3) == 0) {
                int r = rb + wr * 32 + (ri >> 1) * 16 + (ri & 1) * 8 + (lane >> 2);
                g_ps[r][slot] = sv;
            }
        }
        __syncthreads();    // protect smem reuse by next stripe
        tile = tend;
    }
}

// ---------------------------------------------------------------------------
// Kernel 3: per-row loss + fused deterministic mean (last-block reduction)
// loss_row = ln2 * (log2(S - 2^diag) - pos)
// ---------------------------------------------------------------------------
__global__ __launch_bounds__(256) void k_red(float* __restrict__ out)
{
    int t = threadIdx.x;
    int r = blockIdx.x * 256 + t;

    const float4* p4 = (const float4*)g_ps[r];
    float4 v0 = p4[0], v1 = p4[1], v2 = p4[2], v3 = p4[3];
    float S = ((v0.x + v0.y) + (v0.z + v0.w)) + ((v1.x + v1.y) + (v1.z + v1.w))
            + ((v2.x + v2.y) + (v2.z + v2.w)) + ((v3.x + v3.y) + (v3.z + v3.w));
    S -= ex2f(g_diag[r]);
    float acc = lg2f(S) - g_pos[r];

    #pragma unroll
    for (int o = 16; o > 0; o >>= 1) acc += __shfl_xor_sync(0xFFFFFFFFu, acc, o);
    __shared__ float red[8];
    __shared__ unsigned rank;
    if ((t & 31) == 0) red[t >> 5] = acc;
    __syncthreads();
    if (t < 8) {
        float v = red[t];
        #pragma unroll
        for (int o = 4; o > 0; o >>= 1) v += __shfl_xor_sync(0xFFu, v, o);
        if (t == 0) {
            g_blk[blockIdx.x] = v;
            __threadfence();
            rank = atomicAdd(&g_cnt, 1u);
        }
    }
    __syncthreads();
    if (rank == RBLK - 1 && t < RBLK) {   // last block finishes the mean
        float v = *((volatile float*)&g_blk[t]);
        #pragma unroll
        for (int o = 16; o > 0; o >>= 1) v += __shfl_xor_sync(0xFFFFFFFFu, v, o);
        if (t == 0) out[0] = v * (LN2f / (float)NROWS);
    }
}

// ---------------------------------------------------------------------------
extern "C" void kernel_launch(void* const* d_in, const int* in_sizes, int n_in,
                              void* d_out, int out_size)
{
    const float* ei = (const float*)d_in[0];
    const float* ej = (const float*)d_in[1];
    float* out = (float*)d_out;
    (void)in_sizes; (void)n_in; (void)out_size;

    cudaFuncSetAttribute(k_main, cudaFuncAttributeMaxDynamicSharedMemorySize,
                         SMEM_TOTAL);

    k_prep<<<BATCH / 8, 256>>>(ei, ej);
    k_main<<<GRID, 256, SMEM_TOTAL>>>();
    k_red<<<RBLK, 256>>>(out);
}

// round 14
// speedup vs baseline: 2.4356x; 1.0101x over previous
#include <cuda_runtime.h>
#include <cstdint>
#include <math.h>

// ---------------------------------------------------------------- constants
#define BATCH 4096
#define NROWS 8192
#define DIM   256

#define LN2f  0.69314718055994531f
#define C2    2.8853900817779268f            // 2*log2(e)  (1/T * log2 e, T=0.5)
#define SCALE 1.6986442f                     // sqrt(2*log2 e)

#define BM 128                                // rows per stripe
#define BN 64                                 // cols per tile job
#define NSTRIPE (NROWS / BM)                  // 64
#define NCT     (NROWS / BN)                  // 128 col tiles total
#define TT2     4160                          // triangle jobs: sum_i (128-2i)
#define GRID    296                           // 2 CTAs per SM, exactly

#define PITCH   272                           // smem row pitch (256B data + 16B pad)
#define A_BYTES (BM * PITCH)                  // 34816
#define B_BYTES (BN * PITCH)                  // 17408
#define SMEM_A  0
#define SMEM_B0 A_BYTES
#define SMEM_B1 (A_BYTES + B_BYTES)
#define SMEM_TOTAL (A_BYTES + 2 * B_BYTES)    // 69632 -> 2 CTAs/SM

#define RBLK 32                               // reduce blocks

// ------------------------------------------------------------ device scratch
__device__ __align__(16) uint32_t g_q[NROWS * 64];   // e4m3 rows (64 u32 = 256B)
__device__ float g_s[NROWS];                         // per-row exp2 sums (atomic)
__device__ float g_diag[NROWS];                      // exact fp8 self-logit (log2)
__device__ float g_pos[NROWS];                       // fp32 positive logit (log2)
__device__ float g_blk[RBLK];
__device__ unsigned g_cnt;

// ------------------------------------------------------------- asm helpers
__device__ __forceinline__ uint32_t smem_u32(const void* p) {
    uint32_t a;
    asm("{ .reg .u64 t; cvta.to.shared.u64 t, %1; cvt.u32.u64 %0, t; }" : "=r"(a) : "l"(p));
    return a;
}
__device__ __forceinline__ float ex2f(float x) {
    float y; asm("ex2.approx.ftz.f32 %0, %1;" : "=f"(y) : "f"(x)); return y;
}
__device__ __forceinline__ float lg2f(float x) {
    float y; asm("lg2.approx.f32 %0, %1;" : "=f"(y) : "f"(x)); return y;
}
__device__ __forceinline__ void cp16(uint32_t s, const void* g) {
    asm volatile("cp.async.cg.shared.global [%0], [%1], 16;" :: "r"(s), "l"(g));
}
__device__ __forceinline__ void cp_commit() { asm volatile("cp.async.commit_group;"); }
__device__ __forceinline__ void cp_wait0()  { asm volatile("cp.async.wait_group 0;" ::: "memory"); }
__device__ __forceinline__ void ldmx4(uint32_t* r, uint32_t addr) {
    asm volatile("ldmatrix.sync.aligned.m8n8.x4.shared.b16 {%0,%1,%2,%3}, [%4];"
                 : "=r"(r[0]), "=r"(r[1]), "=r"(r[2]), "=r"(r[3]) : "r"(addr));
}
// FP8 e4m3 MMA, f32 accumulate (plain-target PTX, sm_89+)
__device__ __forceinline__ void mma_fp8(float* c, const uint32_t* a,
                                        uint32_t b0, uint32_t b1) {
    asm volatile("mma.sync.aligned.m16n8k32.row.col.f32.e4m3.e4m3.f32 "
                 "{%0,%1,%2,%3}, {%4,%5,%6,%7}, {%8,%9}, {%0,%1,%2,%3};"
                 : "+f"(c[0]), "+f"(c[1]), "+f"(c[2]), "+f"(c[3])
                 : "r"(a[0]), "r"(a[1]), "r"(a[2]), "r"(a[3]), "r"(b0), "r"(b1));
}
// pack 4 floats -> 4 e4m3 bytes (byte0 = x)
__device__ __forceinline__ uint32_t fp8pack4(float x, float y, float z, float w) {
    uint16_t lo, hi; uint32_t r;
    asm("cvt.rn.satfinite.e4m3x2.f32 %0, %2, %1;" : "=h"(lo) : "f"(x), "f"(y));
    asm("cvt.rn.satfinite.e4m3x2.f32 %0, %2, %1;" : "=h"(hi) : "f"(z), "f"(w));
    asm("mov.b32 %0, {%1, %2};" : "=r"(r) : "h"(lo), "h"(hi));
    return r;
}
// exact dequant: sum of squares of the 4 e4m3 bytes in v (pure PTX)
__device__ __forceinline__ float fp8_sq4(uint32_t v) {
    float f0, f1, f2, f3;
    asm("{ .reg .b16 l, h, a, b, c, d;\n\t"
        "  mov.b32 {l, h}, %4;\n\t"
        "  .reg .b32 p, q;\n\t"
        "  cvt.rn.f16x2.e4m3x2 p, l;\n\t"
        "  cvt.rn.f16x2.e4m3x2 q, h;\n\t"
        "  mov.b32 {a, b}, p;\n\t"
        "  mov.b32 {c, d}, q;\n\t"
        "  cvt.f32.f16 %0, a;\n\t"
        "  cvt.f32.f16 %1, b;\n\t"
        "  cvt.f32.f16 %2, c;\n\t"
        "  cvt.f32.f16 %3, d; }"
        : "=f"(f0), "=f"(f1), "=f"(f2), "=f"(f3) : "r"(v));
    return f0*f0 + f1*f1 + f2*f2 + f3*f3;
}

// ---------------------------------------------------------------------------
// Kernel 1 (prep): one warp per pair (r, r+B).
// ---------------------------------------------------------------------------
__global__ __launch_bounds__(256) void k_prep(const float* __restrict__ ei,
                                              const float* __restrict__ ej)
{
    int w = threadIdx.x >> 5, lane = threadIdx.x & 31;
    int r = blockIdx.x * 8 + w;                 // 0..4095

    int gid = blockIdx.x * 256 + threadIdx.x;
    if (gid < NROWS) g_s[gid] = 0.f;
    if (gid == 0) g_cnt = 0;

    const float4* A4 = (const float4*)(ei + (size_t)r * DIM);
    const float4* B4 = (const float4*)(ej + (size_t)r * DIM);
    float4 a0 = A4[lane], a1 = A4[lane + 32];
    float4 b0 = B4[lane], b1 = B4[lane + 32];

    float na = a0.x*a0.x + a0.y*a0.y + a0.z*a0.z + a0.w*a0.w
             + a1.x*a1.x + a1.y*a1.y + a1.z*a1.z + a1.w*a1.w;
    float nb = b0.x*b0.x + b0.y*b0.y + b0.z*b0.z + b0.w*b0.w
             + b1.x*b1.x + b1.y*b1.y + b1.z*b1.z + b1.w*b1.w;
    float ab = a0.x*b0.x + a0.y*b0.y + a0.z*b0.z + a0.w*b0.w
             + a1.x*b1.x + a1.y*b1.y + a1.z*b1.z + a1.w*b1.w;
    #pragma unroll
    for (int o = 16; o > 0; o >>= 1) {
        na += __shfl_xor_sync(0xFFFFFFFFu, na, o);
        nb += __shfl_xor_sync(0xFFFFFFFFu, nb, o);
        ab += __shfl_xor_sync(0xFFFFFFFFu, ab, o);
    }
    float inva = rsqrtf(na) * SCALE;
    float invb = rsqrtf(nb) * SCALE;

    uint32_t qa0 = fp8pack4(a0.x*inva, a0.y*inva, a0.z*inva, a0.w*inva);
    uint32_t qa1 = fp8pack4(a1.x*inva, a1.y*inva, a1.z*inva, a1.w*inva);
    uint32_t qb0 = fp8pack4(b0.x*invb, b0.y*invb, b0.z*invb, b0.w*invb);
    uint32_t qb1 = fp8pack4(b1.x*invb, b1.y*invb, b1.z*invb, b1.w*invb);

    g_q[(size_t)r * 64 + lane]                    = qa0;
    g_q[(size_t)r * 64 + lane + 32]               = qa1;
    g_q[(size_t)(r + BATCH) * 64 + lane]          = qb0;
    g_q[(size_t)(r + BATCH) * 64 + lane + 32]     = qb1;

    float fda = fp8_sq4(qa0) + fp8_sq4(qa1);
    float fdb = fp8_sq4(qb0) + fp8_sq4(qb1);
    #pragma unroll
    for (int o = 16; o > 0; o >>= 1) {
        fda += __shfl_xor_sync(0xFFFFFFFFu, fda, o);
        fdb += __shfl_xor_sync(0xFFFFFFFFu, fdb, o);
    }
    if (lane == 0) {
        float pos = C2 * ab * rsqrtf(na * nb);
        g_pos[r] = pos;
        g_pos[r + BATCH] = pos;
        g_diag[r]         = fda;
        g_diag[r + BATCH] = fdb;
    }
}

// ---------------------------------------------------------------------------
// Kernel 2: persistent TRIANGULAR fp8 MMA z z^T + dual (row+col) exp2-sums.
// Jobs: (stripe i, col tile ct >= 2i); S(i) = i*(129-i); TT2 = 4160.
// Each upper off-diagonal element contributes 2^u to row r AND row c
// (fp8 dot is exactly symmetric). Diagonal-overlap tiles (ct = 2i, 2i+1)
// use a masked path: row if jc >= ir, col if jc > ir.
// acc layout: L = mb*16 + blk*4 + e;
//   row = rb + wr*32 + mb*16 + (e>>1)*8 + (lane>>2)
//   col = ct*64 + wc*32 + blk*8 + (lane&3)*2 + (e&1)
// ---------------------------------------------------------------------------
__global__ __launch_bounds__(256, 2) void k_main()
{
    extern __shared__ char sm[];
    const uint32_t sb = smem_u32(sm);
    const int t = threadIdx.x, lane = t & 31, wid = t >> 5;
    const int wr = wid >> 1, wc = wid & 1;
    const int c = blockIdx.x;

    const int t0 = (int)(((long long)c * TT2) / GRID);
    const int t1 = (int)(((long long)(c + 1) * TT2) / GRID);

    const uint32_t a_addr0 = sb + SMEM_A
        + (uint32_t)((wr * 32 + (lane & 15)) * PITCH) + (uint32_t)((lane >> 4) * 16);
    const uint32_t a_addr1 = a_addr0 + 16 * PITCH;
    const int nsub = ((lane >> 4) << 3) + (lane & 7);
    const uint32_t bko = (uint32_t)(((lane >> 3) & 1) * 16);
    const uint32_t b_off0 = (uint32_t)((wc * 32 + nsub) * PITCH) + bko;
    const uint32_t b_off1 = (uint32_t)((wc * 32 + 16 + nsub) * PITCH) + bko;

    int job = t0;
    while (job < t1) {
        // stripe index from job via S(i) = i*(129-i), with integer fixup
        int i = (int)((129.0f - sqrtf(16641.0f - 4.0f * (float)job)) * 0.5f);
        i = max(0, min(63, i));
        while (i < 63 && (i + 1) * (129 - (i + 1)) <= job) ++i;
        while (i > 0 && i * (129 - i) > job) --i;
        const int sbase = i * (129 - i);
        const int jend = min(t1, sbase + (128 - 2 * i));
        const int rb = i * BM;

        // load A stripe + first B tile
        {
            const char* ga = (const char*)g_q + (size_t)rb * 256;
            #pragma unroll
            for (int it = 0; it < 8; ++it) {
                int idx = t + it * 256;
                int row = idx >> 4, ck = idx & 15;
                cp16(sb + SMEM_A + row * PITCH + ck * 16, ga + row * 256 + ck * 16);
            }
            const int ct0 = 2 * i + (job - sbase);
            const char* gb = (const char*)g_q + (size_t)ct0 * BN * 256;
            #pragma unroll
            for (int it = 0; it < 4; ++it) {
                int idx = t + it * 256;
                int row = idx >> 4, ck = idx & 15;
                cp16(sb + SMEM_B0 + row * PITCH + ck * 16, gb + row * 256 + ck * 16);
            }
            cp_commit(); cp_wait0(); __syncthreads();
        }

        float s_row[4] = {0.f, 0.f, 0.f, 0.f};

        #pragma unroll 1
        for (int jj = job; jj < jend; ++jj) {
            const int ct = 2 * i + (jj - sbase);
            const int ib = (jj - job) & 1;
            const uint32_t bbase = sb + (ib ? SMEM_B1 : SMEM_B0);
            const bool pf = (jj + 1 < jend);

            if (pf) {
                const char* gb = (const char*)g_q + (size_t)(ct + 1) * BN * 256;
                const uint32_t bdst = sb + (ib ? SMEM_B0 : SMEM_B1);
                #pragma unroll
                for (int it = 0; it < 4; ++it) {
                    int idx = t + it * 256;
                    int row = idx >> 4, ck = idx & 15;
                    cp16(bdst + row * PITCH + ck * 16, gb + row * 256 + ck * 16);
                }
                cp_commit();
            }

            float acc[32];
            #pragma unroll
            for (int e = 0; e < 32; ++e) acc[e] = 0.f;

            #pragma unroll
            for (int ks = 0; ks < 8; ++ks) {
                uint32_t af0[4], af1[4], bf0[4], bf1[4];
                ldmx4(af0, a_addr0 + ks * 32);
                ldmx4(af1, a_addr1 + ks * 32);
                ldmx4(bf0, bbase + b_off0 + ks * 32);
                ldmx4(bf1, bbase + b_off1 + ks * 32);
                mma_fp8(acc + 0,  af0, bf0[0], bf0[1]);
                mma_fp8(acc + 4,  af0, bf0[2], bf0[3]);
                mma_fp8(acc + 8,  af0, bf1[0], bf1[1]);
                mma_fp8(acc + 12, af0, bf1[2], bf1[3]);
                mma_fp8(acc + 16, af1, bf0[0], bf0[1]);
                mma_fp8(acc + 20, af1, bf0[2], bf0[3]);
                mma_fp8(acc + 24, af1, bf1[0], bf1[1]);
                mma_fp8(acc + 28, af1, bf1[2], bf1[3]);
            }

            // epilogue: row sums + column-bin partials
            const int cbw = ct * BN + wc * 32;
            float cp[8];
            #pragma unroll
            for (int b = 0; b < 8; ++b) cp[b] = 0.f;

            if (ct >= 2 * i + 2) {
                // strictly-upper tile: unmasked dual contribution
                #pragma unroll
                for (int L = 0; L < 32; ++L) {
                    float e = ex2f(acc[L]);
                    s_row[(L >> 4) * 2 + ((L & 3) >> 1)] += e;
                    cp[((L >> 2) & 3) * 2 + (L & 1)] += e;
                }
            } else {
                // diagonal-overlap tile: mask below-diagonal
                #pragma unroll
                for (int L = 0; L < 32; ++L) {
                    int ir = rb + wr * 32 + (L >> 4) * 16 + ((L & 3) >> 1) * 8 + (lane >> 2);
                    int jc = cbw + ((L >> 2) & 3) * 8 + (lane & 3) * 2 + (L & 1);
                    float e = ex2f(acc[L]);
                    if (jc >= ir) s_row[(L >> 4) * 2 + ((L & 3) >> 1)] += e;
                    if (jc >  ir) cp[((L >> 2) & 3) * 2 + (L & 1)] += e;
                }
            }

            // column reduce over lane bits 2..4 (the 8 row-groups)
            #pragma unroll
            for (int b = 0; b < 8; ++b) {
                cp[b] += __shfl_xor_sync(0xFFFFFFFFu, cp[b], 4);
                cp[b] += __shfl_xor_sync(0xFFFFFFFFu, cp[b], 8);
                cp[b] += __shfl_xor_sync(0xFFFFFFFFu, cp[b], 16);
            }
            if (lane < 4) {
                #pragma unroll
                for (int b = 0; b < 8; ++b) {
                    int col = cbw + (b >> 1) * 8 + lane * 2 + (b & 1);
                    atomicAdd(&g_s[col], cp[b]);
                }
            }

            if (pf) { cp_wait0(); __syncthreads(); }
        }

        // row flush: 4 lanes share each row
        #pragma unroll
        for (int ri = 0; ri < 4; ++ri) {
            float sv = s_row[ri];
            sv += __shfl_xor_sync(0xFFFFFFFFu, sv, 1);
            sv += __shfl_xor_sync(0xFFFFFFFFu, sv, 2);
            if ((lane & 3) == 0) {
                int r = rb + wr * 32 + (ri >> 1) * 16 + (ri & 1) * 8 + (lane >> 2);
                atomicAdd(&g_s[r], sv);
            }
        }
        __syncthreads();    // protect smem reuse by next stripe
        job = jend;
    }
}

// ---------------------------------------------------------------------------
// Kernel 3: per-row loss + fused deterministic mean (last-block reduction)
// loss_row = ln2 * (log2(S - 2^diag) - pos)
// ---------------------------------------------------------------------------
__global__ __launch_bounds__(256) void k_red(float* __restrict__ out)
{
    int t = threadIdx.x;
    int r = blockIdx.x * 256 + t;

    float S = g_s[r] - ex2f(g_diag[r]);
    float acc = lg2f(S) - g_pos[r];

    #pragma unroll
    for (int o = 16; o > 0; o >>= 1) acc += __shfl_xor_sync(0xFFFFFFFFu, acc, o);
    __shared__ float red[8];
    __shared__ unsigned rank;
    if ((t & 31) == 0) red[t >> 5] = acc;
    __syncthreads();
    if (t < 8) {
        float v = red[t];
        #pragma unroll
        for (int o = 4; o > 0; o >>= 1) v += __shfl_xor_sync(0xFFu, v, o);
        if (t == 0) {
            g_blk[blockIdx.x] = v;
            __threadfence();
            rank = atomicAdd(&g_cnt, 1u);
        }
    }
    __syncthreads();
    if (rank == RBLK - 1 && t < RBLK) {   // last block finishes the mean
        float v = *((volatile float*)&g_blk[t]);
        #pragma unroll
        for (int o = 16; o > 0; o >>= 1) v += __shfl_xor_sync(0xFFFFFFFFu, v, o);
        if (t == 0) out[0] = v * (LN2f / (float)NROWS);
    }
}

// ---------------------------------------------------------------------------
extern "C" void kernel_launch(void* const* d_in, const int* in_sizes, int n_in,
                              void* d_out, int out_size)
{
    const float* ei = (const float*)d_in[0];
    const float* ej = (const float*)d_in[1];
    float* out = (float*)d_out;
    (void)in_sizes; (void)n_in; (void)out_size;

    cudaFuncSetAttribute(k_main, cudaFuncAttributeMaxDynamicSharedMemorySize,
                         SMEM_TOTAL);

    k_prep<<<BATCH / 8, 256>>>(ei, ej);
    k_main<<<GRID, 256, SMEM_TOTAL>>>();
    k_red<<<RBLK, 256>>>(out);
}

// round 15
// speedup vs baseline: 3.6306x; 1.4906x over previous
#include <cuda_runtime.h>
#include <cstdint>
#include <math.h>

// ---------------------------------------------------------------- constants
#define BATCH 4096
#define NROWS 8192
#define DIM   256

#define LN2f  0.69314718055994531f
#define C2    2.8853900817779268f            // 2*log2(e)  (1/T * log2 e, T=0.5)
#define SCALE 1.6986442f                     // sqrt(2*log2 e)

#define BM 128                                // rows per stripe
#define BN 64                                 // cols per tile job
#define NSTRIPE (NROWS / BM)                  // 64
#define TT2     4160                          // triangle jobs: sum_i (128-2i)
#define GRID    296                           // 2 CTAs per SM, exactly

#define PITCH   272                           // smem row pitch (256B data + 16B pad)
#define A_BYTES (BM * PITCH)                  // 34816
#define B_BYTES (BN * PITCH)                  // 17408
#define SMEM_A  0
#define SMEM_B0 A_BYTES
#define SMEM_B1 (A_BYTES + B_BYTES)
#define SMEM_TOTAL (A_BYTES + 2 * B_BYTES)    // 69632 -> 2 CTAs/SM

#define RBLK 32                               // reduce blocks

// ------------------------------------------------------------ device scratch
__device__ __align__(16) uint32_t g_q[NROWS * 64];   // e4m3 rows (64 u32 = 256B)
__device__ float g_s[NROWS];                         // per-row exp2 sums (atomic)
__device__ float g_diag[NROWS];                      // exact fp8 self-logit (log2)
__device__ float g_pos[NROWS];                       // fp32 positive logit (log2)
__device__ float g_blk[RBLK];
__device__ unsigned g_cnt;

// ------------------------------------------------------------- asm helpers
__device__ __forceinline__ uint32_t smem_u32(const void* p) {
    uint32_t a;
    asm("{ .reg .u64 t; cvta.to.shared.u64 t, %1; cvt.u32.u64 %0, t; }" : "=r"(a) : "l"(p));
    return a;
}
__device__ __forceinline__ float ex2f(float x) {
    float y; asm("ex2.approx.ftz.f32 %0, %1;" : "=f"(y) : "f"(x)); return y;
}
__device__ __forceinline__ float lg2f(float x) {
    float y; asm("lg2.approx.f32 %0, %1;" : "=f"(y) : "f"(x)); return y;
}
__device__ __forceinline__ void cp16(uint32_t s, const void* g) {
    asm volatile("cp.async.cg.shared.global [%0], [%1], 16;" :: "r"(s), "l"(g));
}
__device__ __forceinline__ void cp_commit() { asm volatile("cp.async.commit_group;"); }
__device__ __forceinline__ void cp_wait0()  { asm volatile("cp.async.wait_group 0;" ::: "memory"); }
__device__ __forceinline__ void ldmx4(uint32_t* r, uint32_t addr) {
    asm volatile("ldmatrix.sync.aligned.m8n8.x4.shared.b16 {%0,%1,%2,%3}, [%4];"
                 : "=r"(r[0]), "=r"(r[1]), "=r"(r[2]), "=r"(r[3]) : "r"(addr));
}
__device__ __forceinline__ void mma_fp8(float* c, const uint32_t* a,
                                        uint32_t b0, uint32_t b1) {
    asm volatile("mma.sync.aligned.m16n8k32.row.col.f32.e4m3.e4m3.f32 "
                 "{%0,%1,%2,%3}, {%4,%5,%6,%7}, {%8,%9}, {%0,%1,%2,%3};"
                 : "+f"(c[0]), "+f"(c[1]), "+f"(c[2]), "+f"(c[3])
                 : "r"(a[0]), "r"(a[1]), "r"(a[2]), "r"(a[3]), "r"(b0), "r"(b1));
}
__device__ __forceinline__ uint32_t fp8pack4(float x, float y, float z, float w) {
    uint16_t lo, hi; uint32_t r;
    asm("cvt.rn.satfinite.e4m3x2.f32 %0, %2, %1;" : "=h"(lo) : "f"(x), "f"(y));
    asm("cvt.rn.satfinite.e4m3x2.f32 %0, %2, %1;" : "=h"(hi) : "f"(z), "f"(w));
    asm("mov.b32 %0, {%1, %2};" : "=r"(r) : "h"(lo), "h"(hi));
    return r;
}
__device__ __forceinline__ float fp8_sq4(uint32_t v) {
    float f0, f1, f2, f3;
    asm("{ .reg .b16 l, h, a, b, c, d;\n\t"
        "  mov.b32 {l, h}, %4;\n\t"
        "  .reg .b32 p, q;\n\t"
        "  cvt.rn.f16x2.e4m3x2 p, l;\n\t"
        "  cvt.rn.f16x2.e4m3x2 q, h;\n\t"
        "  mov.b32 {a, b}, p;\n\t"
        "  mov.b32 {c, d}, q;\n\t"
        "  cvt.f32.f16 %0, a;\n\t"
        "  cvt.f32.f16 %1, b;\n\t"
        "  cvt.f32.f16 %2, c;\n\t"
        "  cvt.f32.f16 %3, d; }"
        : "=f"(f0), "=f"(f1), "=f"(f2), "=f"(f3) : "r"(v));
    return f0*f0 + f1*f1 + f2*f2 + f3*f3;
}

// ---------------------------------------------------------------------------
// Kernel 1 (prep): one warp per pair (r, r+B). (unchanged)
// ---------------------------------------------------------------------------
__global__ __launch_bounds__(256) void k_prep(const float* __restrict__ ei,
                                              const float* __restrict__ ej)
{
    int w = threadIdx.x >> 5, lane = threadIdx.x & 31;
    int r = blockIdx.x * 8 + w;

    int gid = blockIdx.x * 256 + threadIdx.x;
    if (gid < NROWS) g_s[gid] = 0.f;
    if (gid == 0) g_cnt = 0;

    const float4* A4 = (const float4*)(ei + (size_t)r * DIM);
    const float4* B4 = (const float4*)(ej + (size_t)r * DIM);
    float4 a0 = A4[lane], a1 = A4[lane + 32];
    float4 b0 = B4[lane], b1 = B4[lane + 32];

    float na = a0.x*a0.x + a0.y*a0.y + a0.z*a0.z + a0.w*a0.w
             + a1.x*a1.x + a1.y*a1.y + a1.z*a1.z + a1.w*a1.w;
    float nb = b0.x*b0.x + b0.y*b0.y + b0.z*b0.z + b0.w*b0.w
             + b1.x*b1.x + b1.y*b1.y + b1.z*b1.z + b1.w*b1.w;
    float ab = a0.x*b0.x + a0.y*b0.y + a0.z*b0.z + a0.w*b0.w
             + a1.x*b1.x + a1.y*b1.y + a1.z*b1.z + a1.w*b1.w;
    #pragma unroll
    for (int o = 16; o > 0; o >>= 1) {
        na += __shfl_xor_sync(0xFFFFFFFFu, na, o);
        nb += __shfl_xor_sync(0xFFFFFFFFu, nb, o);
        ab += __shfl_xor_sync(0xFFFFFFFFu, ab, o);
    }
    float inva = rsqrtf(na) * SCALE;
    float invb = rsqrtf(nb) * SCALE;

    uint32_t qa0 = fp8pack4(a0.x*inva, a0.y*inva, a0.z*inva, a0.w*inva);
    uint32_t qa1 = fp8pack4(a1.x*inva, a1.y*inva, a1.z*inva, a1.w*inva);
    uint32_t qb0 = fp8pack4(b0.x*invb, b0.y*invb, b0.z*invb, b0.w*invb);
    uint32_t qb1 = fp8pack4(b1.x*invb, b1.y*invb, b1.z*invb, b1.w*invb);

    g_q[(size_t)r * 64 + lane]                    = qa0;
    g_q[(size_t)r * 64 + lane + 32]               = qa1;
    g_q[(size_t)(r + BATCH) * 64 + lane]          = qb0;
    g_q[(size_t)(r + BATCH) * 64 + lane + 32]     = qb1;

    float fda = fp8_sq4(qa0) + fp8_sq4(qa1);
    float fdb = fp8_sq4(qb0) + fp8_sq4(qb1);
    #pragma unroll
    for (int o = 16; o > 0; o >>= 1) {
        fda += __shfl_xor_sync(0xFFFFFFFFu, fda, o);
        fdb += __shfl_xor_sync(0xFFFFFFFFu, fdb, o);
    }
    if (lane == 0) {
        float pos = C2 * ab * rsqrtf(na * nb);
        g_pos[r] = pos;
        g_pos[r + BATCH] = pos;
        g_diag[r]         = fda;
        g_diag[r + BATCH] = fdb;
    }
}

// ---------------------------------------------------------------------------
// helpers for k_main
// ---------------------------------------------------------------------------
__device__ __forceinline__ void prefetch_b(int ct_next, uint32_t bdst, int t)
{
    const char* gb = (const char*)g_q + (size_t)ct_next * BN * 256;
    #pragma unroll
    for (int it = 0; it < 4; ++it) {
        int idx = t + it * 256;
        int row = idx >> 4, ck = idx & 15;
        cp16(bdst + row * PITCH + ck * 16, gb + row * 256 + ck * 16);
    }
    cp_commit();
}

// MMA over one 128x64 tile; if PEND, interleave prev tile's exp2 accumulation
// (4 elements per k-step into s_row and col bins cp).
template <bool PEND>
__device__ __forceinline__ void mma_tile(
    uint32_t bbase, uint32_t a_addr0, uint32_t a_addr1,
    uint32_t b_off0, uint32_t b_off1,
    float* accC, const float* accP, float* s_row, float* cp)
{
    #pragma unroll
    for (int e = 0; e < 32; ++e) accC[e] = 0.f;
    #pragma unroll
    for (int ks = 0; ks < 8; ++ks) {
        uint32_t af0[4], af1[4], bf0[4], bf1[4];
        ldmx4(af0, a_addr0 + ks * 32);
        ldmx4(af1, a_addr1 + ks * 32);
        ldmx4(bf0, bbase + b_off0 + ks * 32);
        ldmx4(bf1, bbase + b_off1 + ks * 32);
        mma_fp8(accC + 0,  af0, bf0[0], bf0[1]);
        mma_fp8(accC + 4,  af0, bf0[2], bf0[3]);
        mma_fp8(accC + 8,  af0, bf1[0], bf1[1]);
        mma_fp8(accC + 12, af0, bf1[2], bf1[3]);
        mma_fp8(accC + 16, af1, bf0[0], bf0[1]);
        mma_fp8(accC + 20, af1, bf0[2], bf0[3]);
        mma_fp8(accC + 24, af1, bf1[0], bf1[1]);
        mma_fp8(accC + 28, af1, bf1[2], bf1[3]);
        if (PEND) {
            #pragma unroll
            for (int j = 0; j < 4; ++j) {
                const int L = ks * 4 + j;
                float e = ex2f(accP[L]);
                s_row[(L >> 4) * 2 + ((L & 3) >> 1)] += e;
                cp[((L >> 2) & 3) * 2 + (L & 1)] += e;
            }
        }
    }
}

// reduce col bins over lane bits 2..4, atomically add into g_s
__device__ __forceinline__ void col_flush(float* cp, int cbw, int lane)
{
    #pragma unroll
    for (int b = 0; b < 8; ++b) {
        cp[b] += __shfl_xor_sync(0xFFFFFFFFu, cp[b], 4);
        cp[b] += __shfl_xor_sync(0xFFFFFFFFu, cp[b], 8);
        cp[b] += __shfl_xor_sync(0xFFFFFFFFu, cp[b], 16);
    }
    if (lane < 4) {
        #pragma unroll
        for (int b = 0; b < 8; ++b)
            atomicAdd(&g_s[cbw + (b >> 1) * 8 + lane * 2 + (b & 1)], cp[b]);
    }
}

// full (non-interleaved) dual epilogue for one tile
__device__ __forceinline__ void epi_dual(const float* acc, float* s_row,
                                         int cbw, int lane)
{
    float cp[8];
    #pragma unroll
    for (int b = 0; b < 8; ++b) cp[b] = 0.f;
    #pragma unroll
    for (int L = 0; L < 32; ++L) {
        float e = ex2f(acc[L]);
        s_row[(L >> 4) * 2 + ((L & 3) >> 1)] += e;
        cp[((L >> 2) & 3) * 2 + (L & 1)] += e;
    }
    col_flush(cp, cbw, lane);
}

// masked epilogue for diagonal-overlap tiles
__device__ __forceinline__ void epi_masked(const float* acc, float* s_row,
                                           int rb, int wr, int cbw, int lane)
{
    float cp[8];
    #pragma unroll
    for (int b = 0; b < 8; ++b) cp[b] = 0.f;
    #pragma unroll
    for (int L = 0; L < 32; ++L) {
        int ir = rb + wr * 32 + (L >> 4) * 16 + ((L & 3) >> 1) * 8 + (lane >> 2);
        int jc = cbw + ((L >> 2) & 3) * 8 + (lane & 3) * 2 + (L & 1);
        float e = ex2f(acc[L]);
        if (jc >= ir) s_row[(L >> 4) * 2 + ((L & 3) >> 1)] += e;
        if (jc >  ir) cp[((L >> 2) & 3) * 2 + (L & 1)] += e;
    }
    col_flush(cp, cbw, lane);
}

// ---------------------------------------------------------------------------
// Kernel 2: persistent TRIANGULAR fp8 MMA with deferred dual epilogue.
// Jobs: (stripe i, ct >= 2i); masked tiles (ct < 2i+2) handled in a prologue,
// remaining tiles run a 2x-unrolled software pipeline (tile m's MMA loop
// hides tile m-1's exp2/row/col accumulation; SHFL+atomic tail overlaps
// the cp.async wait).
// ---------------------------------------------------------------------------
__global__ __launch_bounds__(256, 2) void k_main()
{
    extern __shared__ char sm[];
    const uint32_t sb = smem_u32(sm);
    const int t = threadIdx.x, lane = t & 31, wid = t >> 5;
    const int wr = wid >> 1, wc = wid & 1;
    const int c = blockIdx.x;

    const int t0 = (int)(((long long)c * TT2) / GRID);
    const int t1 = (int)(((long long)(c + 1) * TT2) / GRID);

    const uint32_t a_addr0 = sb + SMEM_A
        + (uint32_t)((wr * 32 + (lane & 15)) * PITCH) + (uint32_t)((lane >> 4) * 16);
    const uint32_t a_addr1 = a_addr0 + 16 * PITCH;
    const int nsub = ((lane >> 4) << 3) + (lane & 7);
    const uint32_t bko = (uint32_t)(((lane >> 3) & 1) * 16);
    const uint32_t b_off0 = (uint32_t)((wc * 32 + nsub) * PITCH) + bko;
    const uint32_t b_off1 = (uint32_t)((wc * 32 + 16 + nsub) * PITCH) + bko;

    int job = t0;
    while (job < t1) {
        int i = (int)((129.0f - sqrtf(16641.0f - 4.0f * (float)job)) * 0.5f);
        i = max(0, min(63, i));
        while (i < 63 && (i + 1) * (129 - (i + 1)) <= job) ++i;
        while (i > 0 && i * (129 - i) > job) --i;
        const int sbase = i * (129 - i);
        const int jend = min(t1, sbase + (128 - 2 * i));
        const int rb = i * BM;

        // load A stripe + first B tile
        {
            const char* ga = (const char*)g_q + (size_t)rb * 256;
            #pragma unroll
            for (int it = 0; it < 8; ++it) {
                int idx = t + it * 256;
                int row = idx >> 4, ck = idx & 15;
                cp16(sb + SMEM_A + row * PITCH + ck * 16, ga + row * 256 + ck * 16);
            }
            prefetch_b(2 * i + (job - sbase), sb + SMEM_B0, t);
            cp_wait0(); __syncthreads();
        }

        float s_row[4] = {0.f, 0.f, 0.f, 0.f};
        float acc0[32], acc1[32];
        float cp[8];

        int jj = job;

        // ---- masked prologue tiles (at most 2, only at stripe start) ----
        while (jj < jend && (jj - sbase) < 2) {
            const int ct = 2 * i + (jj - sbase);
            const uint32_t bbase = sb + (((jj - job) & 1) ? SMEM_B1 : SMEM_B0);
            const bool pf = (jj + 1 < jend);
            if (pf)
                prefetch_b(ct + 1, sb + (((jj + 1 - job) & 1) ? SMEM_B1 : SMEM_B0), t);
            mma_tile<false>(bbase, a_addr0, a_addr1, b_off0, b_off1,
                            acc0, acc1, s_row, cp);
            epi_masked(acc0, s_row, rb, wr, ct * BN + wc * 32, lane);
            if (pf) { cp_wait0(); __syncthreads(); }
            ++jj;
        }

        // ---- pipelined unmasked tiles ----
        const int n = jend - jj;
        if (n > 0) {
            // helper lambdas via macros: compute per-tile values from m
            #define CTm(m)   (2 * i + ((jj + (m)) - sbase))
            #define BBASE(m) (sb + ((((jj + (m)) - job) & 1) ? SMEM_B1 : SMEM_B0))
            #define CBW(m)   (CTm(m) * BN + wc * 32)
            #define PF(m)    ((jj + (m) + 1) < jend)

            // fill: tile 0
            if (PF(0)) prefetch_b(CTm(0) + 1, BBASE(1), t);
            mma_tile<false>(BBASE(0), a_addr0, a_addr1, b_off0, b_off1,
                            acc0, acc1, s_row, cp);
            if (PF(0)) { cp_wait0(); __syncthreads(); }

            int k = 1;
            for (; k + 1 < n; k += 2) {
                // tile k: cur acc1, prev acc0
                #pragma unroll
                for (int b = 0; b < 8; ++b) cp[b] = 0.f;
                if (PF(k)) prefetch_b(CTm(k) + 1, BBASE(k + 1), t);
                mma_tile<true>(BBASE(k), a_addr0, a_addr1, b_off0, b_off1,
                               acc1, acc0, s_row, cp);
                col_flush(cp, CBW(k - 1), lane);
                if (PF(k)) { cp_wait0(); __syncthreads(); }

                // tile k+1: cur acc0, prev acc1
                #pragma unroll
                for (int b = 0; b < 8; ++b) cp[b] = 0.f;
                if (PF(k + 1)) prefetch_b(CTm(k + 1) + 1, BBASE(k + 2), t);
                mma_tile<true>(BBASE(k + 1), a_addr0, a_addr1, b_off0, b_off1,
                               acc0, acc1, s_row, cp);
                col_flush(cp, CBW(k), lane);
                if (PF(k + 1)) { cp_wait0(); __syncthreads(); }
            }
            if (k < n) {
                // one more tile: cur acc1, prev acc0; then drain acc1
                #pragma unroll
                for (int b = 0; b < 8; ++b) cp[b] = 0.f;
                if (PF(k)) prefetch_b(CTm(k) + 1, BBASE(k + 1), t);
                mma_tile<true>(BBASE(k), a_addr0, a_addr1, b_off0, b_off1,
                               acc1, acc0, s_row, cp);
                col_flush(cp, CBW(k - 1), lane);
                if (PF(k)) { cp_wait0(); __syncthreads(); }
                epi_dual(acc1, s_row, CBW(k), lane);
            } else {
                // drain acc0 (n == 1 or even-n tail handled above)
                epi_dual(acc0, s_row, CBW(n - 1), lane);
            }
            #undef CTm
            #undef BBASE
            #undef CBW
            #undef PF
        }

        // row flush: 4 lanes share each row
        #pragma unroll
        for (int ri = 0; ri < 4; ++ri) {
            float sv = s_row[ri];
            sv += __shfl_xor_sync(0xFFFFFFFFu, sv, 1);
            sv += __shfl_xor_sync(0xFFFFFFFFu, sv, 2);
            if ((lane & 3) == 0) {
                int r = rb + wr * 32 + (ri >> 1) * 16 + (ri & 1) * 8 + (lane >> 2);
                atomicAdd(&g_s[r], sv);
            }
        }
        __syncthreads();    // protect smem reuse by next stripe
        job = jend;
    }
}

// ---------------------------------------------------------------------------
// Kernel 3: per-row loss + fused deterministic mean (last-block reduction)
// ---------------------------------------------------------------------------
__global__ __launch_bounds__(256) void k_red(float* __restrict__ out)
{
    int t = threadIdx.x;
    int r = blockIdx.x * 256 + t;

    float S = g_s[r] - ex2f(g_diag[r]);
    float acc = lg2f(S) - g_pos[r];

    #pragma unroll
    for (int o = 16; o > 0; o >>= 1) acc += __shfl_xor_sync(0xFFFFFFFFu, acc, o);
    __shared__ float red[8];
    __shared__ unsigned rank;
    if ((t & 31) == 0) red[t >> 5] = acc;
    __syncthreads();
    if (t < 8) {
        float v = red[t];
        #pragma unroll
        for (int o = 4; o > 0; o >>= 1) v += __shfl_xor_sync(0xFFu, v, o);
        if (t == 0) {
            g_blk[blockIdx.x] = v;
            __threadfence();
            rank = atomicAdd(&g_cnt, 1u);
        }
    }
    __syncthreads();
    if (rank == RBLK - 1 && t < RBLK) {
        float v = *((volatile float*)&g_blk[t]);
        #pragma unroll
        for (int o = 16; o > 0; o >>= 1) v += __shfl_xor_sync(0xFFFFFFFFu, v, o);
        if (t == 0) out[0] = v * (LN2f / (float)NROWS);
    }
}

// ---------------------------------------------------------------------------
extern "C" void kernel_launch(void* const* d_in, const int* in_sizes, int n_in,
                              void* d_out, int out_size)
{
    const float* ei = (const float*)d_in[0];
    const float* ej = (const float*)d_in[1];
    float* out = (float*)d_out;
    (void)in_sizes; (void)n_in; (void)out_size;

    cudaFuncSetAttribute(k_main, cudaFuncAttributeMaxDynamicSharedMemorySize,
                         SMEM_TOTAL);

    k_prep<<<BATCH / 8, 256>>>(ei, ej);
    k_main<<<GRID, 256, SMEM_TOTAL>>>();
    k_red<<<RBLK, 256>>>(out);
}